// round 9
// baseline (speedup 1.0000x reference)
#include <cuda_runtime.h>
#include <math.h>

// ---------------------------------------------------------------------------
// Problem constants
// ---------------------------------------------------------------------------
#define BB      2
#define SEQ     2048
#define DMODEL  2048
#define NHEAD   16
#define NKV     4
#define DHEAD   128
#define QINNER  (NHEAD * DHEAD)    // 2048
#define KVINNER (NKV * DHEAD)      // 512
#define NREP    (NHEAD / NKV)      // 4
#define MROWS   (BB * SEQ)         // 4096

// Scratch (allocation-free rule: device globals)
__device__ float g_q[MROWS * QINNER];
__device__ float g_k[MROWS * KVINNER];
__device__ float g_v[MROWS * KVINNER];
__device__ float g_att[MROWS * QINNER];
// tf32-pre-rounded copies of mma inputs (so HW truncation in GEMMs is exact)
__device__ float g_x19[MROWS * DMODEL];
__device__ float g_wq19[QINNER * DMODEL];
__device__ float g_wk19[KVINNER * DMODEL];
__device__ float g_wv19[KVINNER * DMODEL];
__device__ float g_wo19[DMODEL * QINNER];

// ---------------------------------------------------------------------------
// tf32 helpers
// ---------------------------------------------------------------------------
__device__ __forceinline__ float f2tf(float x) {
    unsigned y;
    asm("cvt.rna.tf32.f32 %0, %1;" : "=r"(y) : "f"(x));
    return __uint_as_float(y);
}
__device__ __forceinline__ unsigned f2tfu(float x) {
    unsigned y;
    asm("cvt.rna.tf32.f32 %0, %1;" : "=r"(y) : "f"(x));
    return y;
}

// D += A(16x8) * B(8x8), tf32 inputs, fp32 accum
__device__ __forceinline__ void mma8(float* d, const unsigned* a, const unsigned* b) {
    asm("mma.sync.aligned.m16n8k8.row.col.f32.tf32.tf32.f32 "
        "{%0,%1,%2,%3},{%4,%5,%6,%7},{%8,%9},{%0,%1,%2,%3};"
        : "+f"(d[0]), "+f"(d[1]), "+f"(d[2]), "+f"(d[3])
        : "r"(a[0]), "r"(a[1]), "r"(a[2]), "r"(a[3]), "r"(b[0]), "r"(b[1]));
}

__device__ __forceinline__ void cp16(unsigned s, const void* g) {
    asm volatile("cp.async.cg.shared.global [%0], [%1], 16;\n" :: "r"(s), "l"(g));
}

// ---------------------------------------------------------------------------
// Elementwise RNA round-to-tf32 (float4 vectorized)
// ---------------------------------------------------------------------------
__global__ __launch_bounds__(256)
void round_tf32(const float4* __restrict__ in, float4* __restrict__ out, int n4)
{
    int i = blockIdx.x * blockDim.x + threadIdx.x;
    if (i < n4) {
        float4 v = in[i];
        v.x = f2tf(v.x); v.y = f2tf(v.y); v.z = f2tf(v.z); v.w = f2tf(v.w);
        out[i] = v;
    }
}

// ---------------------------------------------------------------------------
// tf32 GEMM body: C = A @ W^T + bias. Padded smem + cp.async 2-stage pipeline.
// Inputs are pre-rounded to tf32, so HW truncation at the mma is exact RNA.
// 128x128x32 tiles, 8 warps (2 wm x 4 wn), warp = 64x32 via 4x4 m16n8k8.
// ---------------------------------------------------------------------------
#define TBM 128
#define TBN 128
#define TBK 32
#define TPAD 36    // smem leading dim; 36 % 32 = 4 -> conflict-free frag reads
#define GEMM_SMEM (2 * 2 * TBM * TPAD * 4)   // 73728 bytes

__device__ __forceinline__
void gemm_body(const float* __restrict__ A, const float* __restrict__ W,
               const float* __restrict__ bias, float* __restrict__ C,
               int N, int K, int bm, int bn, float* As, float* Ws)
{
    const int tid   = threadIdx.x;
    const int lane  = tid & 31;
    const int wid   = tid >> 5;
    const int gID   = lane >> 2;
    const int tig   = lane & 3;
    const int wmSel = wid & 1;
    const int wnSel = wid >> 1;
    const unsigned asb = (unsigned)__cvta_generic_to_shared(As);
    const unsigned wsb = (unsigned)__cvta_generic_to_shared(Ws);

    float acc[4][4][4];
#pragma unroll
    for (int mi = 0; mi < 4; mi++)
#pragma unroll
        for (int ni = 0; ni < 4; ni++)
#pragma unroll
            for (int j = 0; j < 4; j++) acc[mi][ni][j] = 0.f;

    const int NT = K / TBK;

    // prefetch tile 0 into buffer 0
#pragma unroll
    for (int it = 0; it < 4; it++) {
        int idx = tid + it * 256, row = idx >> 3, c4 = (idx & 7) << 2;
        cp16(asb + (unsigned)((row * TPAD + c4) << 2), A + (size_t)(bm + row) * K + c4);
        cp16(wsb + (unsigned)((row * TPAD + c4) << 2), W + (size_t)(bn + row) * K + c4);
    }
    asm volatile("cp.async.commit_group;\n");

    for (int kt = 0; kt < NT; kt++) {
        int buf = kt & 1;
        if (kt + 1 < NT) {
            int k0n = (kt + 1) * TBK, bufn = (kt + 1) & 1;
#pragma unroll
            for (int it = 0; it < 4; it++) {
                int idx = tid + it * 256, row = idx >> 3, c4 = (idx & 7) << 2;
                cp16(asb + (unsigned)(((bufn * TBM + row) * TPAD + c4) << 2),
                     A + (size_t)(bm + row) * K + k0n + c4);
                cp16(wsb + (unsigned)(((bufn * TBM + row) * TPAD + c4) << 2),
                     W + (size_t)(bn + row) * K + k0n + c4);
            }
            asm volatile("cp.async.commit_group;\n");
            asm volatile("cp.async.wait_group 1;\n");
        } else {
            asm volatile("cp.async.wait_group 0;\n");
        }
        __syncthreads();

        const float* Ab = As + buf * TBM * TPAD;
        const float* Wb = Ws + buf * TBM * TPAD;
#pragma unroll
        for (int ks = 0; ks < 4; ks++) {
            unsigned af[4][4], bf[4][2];
#pragma unroll
            for (int mi = 0; mi < 4; mi++) {
                int r = wmSel * 64 + mi * 16 + gID;
                af[mi][0] = __float_as_uint(Ab[r * TPAD + ks * 8 + tig]);
                af[mi][1] = __float_as_uint(Ab[(r + 8) * TPAD + ks * 8 + tig]);
                af[mi][2] = __float_as_uint(Ab[r * TPAD + ks * 8 + tig + 4]);
                af[mi][3] = __float_as_uint(Ab[(r + 8) * TPAD + ks * 8 + tig + 4]);
            }
#pragma unroll
            for (int ni = 0; ni < 4; ni++) {
                int c = wnSel * 32 + ni * 8 + gID;
                bf[ni][0] = __float_as_uint(Wb[c * TPAD + ks * 8 + tig]);
                bf[ni][1] = __float_as_uint(Wb[c * TPAD + ks * 8 + tig + 4]);
            }
#pragma unroll
            for (int mi = 0; mi < 4; mi++)
#pragma unroll
                for (int ni = 0; ni < 4; ni++)
                    mma8(acc[mi][ni], af[mi], bf[ni]);
        }
        __syncthreads();
    }

    const int wm = wmSel * 64;
    const int wn = wnSel * 32;
#pragma unroll
    for (int mi = 0; mi < 4; mi++) {
        int r = bm + wm + mi * 16 + gID;
#pragma unroll
        for (int ni = 0; ni < 4; ni++) {
            int c = bn + wn + ni * 8 + 2 * tig;
            float2 bv = *(const float2*)(bias + c);
            *(float2*)(C + (size_t)r * N + c) =
                make_float2(acc[mi][ni][0] + bv.x, acc[mi][ni][1] + bv.y);
            *(float2*)(C + (size_t)(r + 8) * N + c) =
                make_float2(acc[mi][ni][2] + bv.x, acc[mi][ni][3] + bv.y);
        }
    }
}

// Fused QKV projection: blockIdx.x 0..15 -> Q cols, 16..19 -> K, 20..23 -> V
__global__ __launch_bounds__(256, 2)
void qkv_tf32(const float* __restrict__ x,
              const float* __restrict__ Wq, const float* __restrict__ bq,
              const float* __restrict__ Wk, const float* __restrict__ bk,
              const float* __restrict__ Wv, const float* __restrict__ bv,
              float* __restrict__ qp, float* __restrict__ kp, float* __restrict__ vp)
{
    extern __shared__ float dsm[];
    float* As = dsm;
    float* Ws = dsm + 2 * TBM * TPAD;
    int bx = blockIdx.x;
    const float *W, *bias; float* C; int N, bn;
    if (bx < 16)      { W = Wq; bias = bq; C = qp; N = QINNER;  bn = bx * 128; }
    else if (bx < 20) { W = Wk; bias = bk; C = kp; N = KVINNER; bn = (bx - 16) * 128; }
    else              { W = Wv; bias = bv; C = vp; N = KVINNER; bn = (bx - 20) * 128; }
    gemm_body(x, W, bias, C, N, DMODEL, blockIdx.y * TBM, bn, As, Ws);
}

__global__ __launch_bounds__(256, 2)
void oproj_tf32(const float* __restrict__ A, const float* __restrict__ Wo,
                const float* __restrict__ bo, float* __restrict__ C)
{
    extern __shared__ float dsm[];
    float* As = dsm;
    float* Ws = dsm + 2 * TBM * TPAD;
    gemm_body(A, Wo, bo, C, DMODEL, QINNER, blockIdx.y * TBM, blockIdx.x * TBN, As, Ws);
}

// ---------------------------------------------------------------------------
// tf32 flash attention with fragment-major K/V smem (unchanged except the
// epilogue stores att pre-rounded to tf32 for the O-projection).
// ---------------------------------------------------------------------------
#define ABQ  128
#define ABK  64
#define PPAD 68
#define KF_U4 (16 * 4 * 32)     // 2048 uint4 = 32KB
#define VF_U4 (8 * 8 * 32)      // 2048 uint4 = 32KB
#define SMEM_ATTN ((KF_U4 + VF_U4) * 16 + ABQ * PPAD * (int)sizeof(float))

__global__ __launch_bounds__(256, 1)
void attn_tf32(const int* __restrict__ mask)
{
    extern __shared__ float sm[];
    uint4* Kf = (uint4*)sm;
    uint4* Vf = Kf + KF_U4;
    float* Kff = (float*)Kf;
    float* Vff = (float*)Vf;
    float* Ps  = (float*)(Vf + VF_U4);   // [128][PPAD]

    const int tid  = threadIdx.x;
    const int lane = tid & 31;
    const int wid  = tid >> 5;
    const int gID  = lane >> 2;
    const int tig  = lane & 3;
    const int q0   = blockIdx.x * ABQ;
    const int bh   = blockIdx.y;
    const int b    = bh >> 4;
    const int h    = bh & 15;
    const int kh   = h >> 2;
    const float scale = 0.08838834764831845f;   // 1/sqrt(128)

    // ---- Q fragments in registers (rows qr0 = q0+16w+gID, qr0+8) ----
    const int qr0 = q0 + wid * 16 + gID;
    const float* qb0 = g_q + (size_t)(b * SEQ + qr0) * QINNER + h * DHEAD;
    const float* qb1 = qb0 + 8 * QINNER;
    unsigned qa[16][4];
#pragma unroll
    for (int ks = 0; ks < 16; ks++) {
        qa[ks][0] = f2tfu(qb0[ks * 8 + tig]);
        qa[ks][1] = f2tfu(qb1[ks * 8 + tig]);
        qa[ks][2] = f2tfu(qb0[ks * 8 + tig + 4]);
        qa[ks][3] = f2tfu(qb1[ks * 8 + tig + 4]);
    }

    float o[16][4];
#pragma unroll
    for (int n = 0; n < 16; n++)
#pragma unroll
        for (int j = 0; j < 4; j++) o[n][j] = 0.f;
    float m0 = -1e30f, m1 = -1e30f, l0 = 0.f, l1 = 0.f;

    const int* mrow0 = mask + (size_t)b * SEQ * SEQ + (size_t)qr0 * SEQ;
    const int* mrow1 = mrow0 + 8 * SEQ;

    float* prow0 = Ps + (wid * 16 + gID) * PPAD;
    float* prow1 = prow0 + 8 * PPAD;

    const int f_ks  = lane >> 1;
    const int f_half = lane & 1;
    const int f_ni  = lane >> 1;
    const int f_nip = lane >> 2;

    for (int k0 = 0; k0 < SEQ; k0 += ABK) {
        __syncthreads();
        // ---- fill K/V fragment-major tiles (tf32-converted) ----
#pragma unroll
        for (int it = 0; it < 8; it++) {
            int r = wid + it * 8;
            size_t goff = (size_t)(b * SEQ + k0 + r) * KVINNER + kh * DHEAD + lane * 4;
            {
                int ni  = r >> 3, gK = r & 7, nip = ni >> 1;
                int kbase = ((f_ks * 4 + nip) * 32) * 4 + f_half + ((ni & 1) << 1);
                int sw = f_ks & 7;
                float4 kv = *(const float4*)(g_k + goff);
                Kff[kbase + (((gK << 2) | 0) ^ sw) * 4] = f2tf(kv.x);
                Kff[kbase + (((gK << 2) | 1) ^ sw) * 4] = f2tf(kv.y);
                Kff[kbase + (((gK << 2) | 2) ^ sw) * 4] = f2tf(kv.z);
                Kff[kbase + (((gK << 2) | 3) ^ sw) * 4] = f2tf(kv.w);
            }
            {
                int ks2 = r >> 3, tigv = r & 3, halfv = (r >> 2) & 1;
                int vbase = ((ks2 * 8 + f_nip) * 32) * 4 + halfv + ((f_ni & 1) << 1);
                int sw = f_nip & 7;
                int g0 = (lane & 1) << 2;
                float4 vv = *(const float4*)(g_v + goff);
                Vff[vbase + ((((g0 | 0) << 2) | tigv) ^ sw) * 4] = f2tf(vv.x);
                Vff[vbase + ((((g0 | 1) << 2) | tigv) ^ sw) * 4] = f2tf(vv.y);
                Vff[vbase + ((((g0 | 2) << 2) | tigv) ^ sw) * 4] = f2tf(vv.z);
                Vff[vbase + ((((g0 | 3) << 2) | tigv) ^ sw) * 4] = f2tf(vv.w);
            }
        }
        __syncthreads();

        // ---- S = Q @ K^T ----
        float s[8][4];
#pragma unroll
        for (int ni = 0; ni < 8; ni++)
#pragma unroll
            for (int j = 0; j < 4; j++) s[ni][j] = 0.f;

#pragma unroll
        for (int ks = 0; ks < 16; ks++) {
            int lsw = lane ^ (ks & 7);
#pragma unroll
            for (int nip = 0; nip < 4; nip++) {
                uint4 kf = Kf[(ks * 4 + nip) * 32 + lsw];
                unsigned bfe[2] = {kf.x, kf.y};
                unsigned bfo[2] = {kf.z, kf.w};
                mma8(s[2 * nip],     qa[ks], bfe);
                mma8(s[2 * nip + 1], qa[ks], bfo);
            }
        }

        // ---- scale + mask + online softmax ----
        float nm0 = m0, nm1 = m1;
#pragma unroll
        for (int ni = 0; ni < 8; ni++) {
            int cc = k0 + ni * 8 + 2 * tig;
            int2 mm0 = *(const int2*)(mrow0 + cc);
            int2 mm1 = *(const int2*)(mrow1 + cc);
            s[ni][0] = mm0.x ? s[ni][0] * scale : -1e30f;
            s[ni][1] = mm0.y ? s[ni][1] * scale : -1e30f;
            s[ni][2] = mm1.x ? s[ni][2] * scale : -1e30f;
            s[ni][3] = mm1.y ? s[ni][3] * scale : -1e30f;
            nm0 = fmaxf(nm0, fmaxf(s[ni][0], s[ni][1]));
            nm1 = fmaxf(nm1, fmaxf(s[ni][2], s[ni][3]));
        }
        nm0 = fmaxf(nm0, __shfl_xor_sync(0xffffffffu, nm0, 1));
        nm0 = fmaxf(nm0, __shfl_xor_sync(0xffffffffu, nm0, 2));
        nm1 = fmaxf(nm1, __shfl_xor_sync(0xffffffffu, nm1, 1));
        nm1 = fmaxf(nm1, __shfl_xor_sync(0xffffffffu, nm1, 2));

        float corr0 = __expf(m0 - nm0);
        float corr1 = __expf(m1 - nm1);
        m0 = nm0; m1 = nm1;

        float rs0 = 0.f, rs1 = 0.f;
#pragma unroll
        for (int ni = 0; ni < 8; ni++) {
            s[ni][0] = (s[ni][0] > -1e29f) ? __expf(s[ni][0] - m0) : 0.f;
            s[ni][1] = (s[ni][1] > -1e29f) ? __expf(s[ni][1] - m0) : 0.f;
            s[ni][2] = (s[ni][2] > -1e29f) ? __expf(s[ni][2] - m1) : 0.f;
            s[ni][3] = (s[ni][3] > -1e29f) ? __expf(s[ni][3] - m1) : 0.f;
            rs0 += s[ni][0] + s[ni][1];
            rs1 += s[ni][2] + s[ni][3];
        }
        rs0 += __shfl_xor_sync(0xffffffffu, rs0, 1);
        rs0 += __shfl_xor_sync(0xffffffffu, rs0, 2);
        rs1 += __shfl_xor_sync(0xffffffffu, rs1, 1);
        rs1 += __shfl_xor_sync(0xffffffffu, rs1, 2);
        l0 = l0 * corr0 + rs0;
        l1 = l1 * corr1 + rs1;

#pragma unroll
        for (int n = 0; n < 16; n++) {
            o[n][0] *= corr0; o[n][1] *= corr0;
            o[n][2] *= corr1; o[n][3] *= corr1;
        }

        // ---- stash P (tf32) in warp-private smem rows ----
#pragma unroll
        for (int ni = 0; ni < 8; ni++) {
            *(float2*)(prow0 + ni * 8 + 2 * tig) = make_float2(f2tf(s[ni][0]), f2tf(s[ni][1]));
            *(float2*)(prow1 + ni * 8 + 2 * tig) = make_float2(f2tf(s[ni][2]), f2tf(s[ni][3]));
        }
        __syncwarp();

        // ---- O += P @ V ----
#pragma unroll
        for (int ks2 = 0; ks2 < 8; ks2++) {
            unsigned pa[4];
            pa[0] = __float_as_uint(prow0[ks2 * 8 + tig]);
            pa[1] = __float_as_uint(prow1[ks2 * 8 + tig]);
            pa[2] = __float_as_uint(prow0[ks2 * 8 + tig + 4]);
            pa[3] = __float_as_uint(prow1[ks2 * 8 + tig + 4]);
#pragma unroll
            for (int nip = 0; nip < 8; nip++) {
                uint4 vf = Vf[(ks2 * 8 + nip) * 32 + (lane ^ nip)];
                unsigned bfe[2] = {vf.x, vf.y};
                unsigned bfo[2] = {vf.z, vf.w};
                mma8(o[2 * nip],     pa, bfe);
                mma8(o[2 * nip + 1], pa, bfo);
            }
        }
    }

    // ---- normalize + store [b,s,h,d], pre-rounded to tf32 for O-proj ----
    float inv0 = (l0 > 0.f) ? (1.f / l0) : 0.f;
    float inv1 = (l1 > 0.f) ? (1.f / l1) : 0.f;
    float* ob0 = g_att + (size_t)(b * SEQ + qr0) * QINNER + h * DHEAD;
    float* ob1 = ob0 + 8 * QINNER;
#pragma unroll
    for (int ni = 0; ni < 16; ni++) {
        *(float2*)(ob0 + ni * 8 + 2 * tig) =
            make_float2(f2tf(o[ni][0] * inv0), f2tf(o[ni][1] * inv0));
        *(float2*)(ob1 + ni * 8 + 2 * tig) =
            make_float2(f2tf(o[ni][2] * inv1), f2tf(o[ni][3] * inv1));
    }
}

// ---------------------------------------------------------------------------
// Launch
// ---------------------------------------------------------------------------
extern "C" void kernel_launch(void* const* d_in, const int* in_sizes, int n_in,
                              void* d_out, int out_size)
{
    const float* x    = (const float*)d_in[0];
    const int*   mask = (const int*)  d_in[1];
    const float* Wq   = (const float*)d_in[2];
    const float* bq   = (const float*)d_in[3];
    const float* Wk   = (const float*)d_in[4];
    const float* bk   = (const float*)d_in[5];
    const float* Wv   = (const float*)d_in[6];
    const float* bv   = (const float*)d_in[7];
    const float* Wo   = (const float*)d_in[8];
    const float* bo   = (const float*)d_in[9];
    float* out = (float*)d_out;

    float *q, *k, *v, *att, *x19, *wq19, *wk19, *wv19, *wo19;
    cudaGetSymbolAddress((void**)&q,    g_q);
    cudaGetSymbolAddress((void**)&k,    g_k);
    cudaGetSymbolAddress((void**)&v,    g_v);
    cudaGetSymbolAddress((void**)&att,  g_att);
    cudaGetSymbolAddress((void**)&x19,  g_x19);
    cudaGetSymbolAddress((void**)&wq19, g_wq19);
    cudaGetSymbolAddress((void**)&wk19, g_wk19);
    cudaGetSymbolAddress((void**)&wv19, g_wv19);
    cudaGetSymbolAddress((void**)&wo19, g_wo19);

    cudaFuncSetAttribute(attn_tf32,  cudaFuncAttributeMaxDynamicSharedMemorySize, SMEM_ATTN);
    cudaFuncSetAttribute(qkv_tf32,   cudaFuncAttributeMaxDynamicSharedMemorySize, GEMM_SMEM);
    cudaFuncSetAttribute(oproj_tf32, cudaFuncAttributeMaxDynamicSharedMemorySize, GEMM_SMEM);

    dim3 thr(256);
    // pre-round mma inputs to tf32 (RNA)
    {
        int n4;
        n4 = MROWS * DMODEL / 4;
        round_tf32<<<(n4 + 255) / 256, thr>>>((const float4*)x,  (float4*)x19,  n4);
        n4 = QINNER * DMODEL / 4;
        round_tf32<<<(n4 + 255) / 256, thr>>>((const float4*)Wq, (float4*)wq19, n4);
        n4 = KVINNER * DMODEL / 4;
        round_tf32<<<(n4 + 255) / 256, thr>>>((const float4*)Wk, (float4*)wk19, n4);
        round_tf32<<<(n4 + 255) / 256, thr>>>((const float4*)Wv, (float4*)wv19, n4);
        n4 = DMODEL * QINNER / 4;
        round_tf32<<<(n4 + 255) / 256, thr>>>((const float4*)Wo, (float4*)wo19, n4);
    }

    qkv_tf32<<<dim3(24, MROWS / TBM), thr, GEMM_SMEM>>>(x19, wq19, bq, wk19, bk, wv19, bv, q, k, v);
    attn_tf32<<<dim3(SEQ / ABQ, BB * NHEAD), thr, SMEM_ATTN>>>(mask);
    oproj_tf32<<<dim3(DMODEL / TBN, MROWS / TBM), thr, GEMM_SMEM>>>(att, wo19, bo, out);
}

// round 10
// speedup vs baseline: 1.0275x; 1.0275x over previous
#include <cuda_runtime.h>
#include <math.h>

// ---------------------------------------------------------------------------
// Problem constants
// ---------------------------------------------------------------------------
#define BB      2
#define SEQ     2048
#define DMODEL  2048
#define NHEAD   16
#define NKV     4
#define DHEAD   128
#define QINNER  (NHEAD * DHEAD)    // 2048
#define KVINNER (NKV * DHEAD)      // 512
#define NREP    (NHEAD / NKV)      // 4
#define MROWS   (BB * SEQ)         // 4096

// Scratch (allocation-free rule: device globals)
__device__ float g_q[MROWS * QINNER];     // tf32-rounded by qkv epilogue
__device__ float g_k[MROWS * KVINNER];    // tf32-rounded
__device__ float g_v[MROWS * KVINNER];    // tf32-rounded
__device__ float g_att[MROWS * QINNER];   // tf32-rounded by attn epilogue
// tf32-pre-rounded copies of GEMM inputs (HW truncation becomes exact RNA)
__device__ float g_x19[MROWS * DMODEL];
__device__ float g_wq19[QINNER * DMODEL];
__device__ float g_wk19[KVINNER * DMODEL];
__device__ float g_wv19[KVINNER * DMODEL];
__device__ float g_wo19[DMODEL * QINNER];

// ---------------------------------------------------------------------------
// tf32 helpers
// ---------------------------------------------------------------------------
__device__ __forceinline__ float f2tf(float x) {
    unsigned y;
    asm("cvt.rna.tf32.f32 %0, %1;" : "=r"(y) : "f"(x));
    return __uint_as_float(y);
}

// D += A(16x8) * B(8x8), tf32 inputs, fp32 accum
__device__ __forceinline__ void mma8(float* d, const unsigned* a, const unsigned* b) {
    asm("mma.sync.aligned.m16n8k8.row.col.f32.tf32.tf32.f32 "
        "{%0,%1,%2,%3},{%4,%5,%6,%7},{%8,%9},{%0,%1,%2,%3};"
        : "+f"(d[0]), "+f"(d[1]), "+f"(d[2]), "+f"(d[3])
        : "r"(a[0]), "r"(a[1]), "r"(a[2]), "r"(a[3]), "r"(b[0]), "r"(b[1]));
}

__device__ __forceinline__ void cp16(unsigned s, const void* g) {
    asm volatile("cp.async.cg.shared.global [%0], [%1], 16;\n" :: "r"(s), "l"(g));
}

// ---------------------------------------------------------------------------
// Fused RNA round-to-tf32 of all five GEMM inputs (one launch)
// ---------------------------------------------------------------------------
#define N4_X   (MROWS * DMODEL / 4)     // 2097152
#define N4_WQ  (QINNER * DMODEL / 4)    // 1048576
#define N4_WKV (KVINNER * DMODEL / 4)   // 262144
#define N4_WO  (DMODEL * QINNER / 4)    // 1048576
#define N4_ALL (N4_X + N4_WQ + 2 * N4_WKV + N4_WO)

__global__ __launch_bounds__(256)
void round_all(const float4* __restrict__ x,  float4* __restrict__ xo,
               const float4* __restrict__ wq, float4* __restrict__ wqo,
               const float4* __restrict__ wk, float4* __restrict__ wko,
               const float4* __restrict__ wv, float4* __restrict__ wvo,
               const float4* __restrict__ wo, float4* __restrict__ woo)
{
    int i = blockIdx.x * blockDim.x + threadIdx.x;
    if (i >= N4_ALL) return;
    const float4* src; float4* dst; int off;
    if (i < N4_X)                            { src = x;  dst = xo;  off = i; }
    else if (i < N4_X + N4_WQ)               { src = wq; dst = wqo; off = i - N4_X; }
    else if (i < N4_X + N4_WQ + N4_WKV)      { src = wk; dst = wko; off = i - N4_X - N4_WQ; }
    else if (i < N4_X + N4_WQ + 2 * N4_WKV)  { src = wv; dst = wvo; off = i - N4_X - N4_WQ - N4_WKV; }
    else                                     { src = wo; dst = woo; off = i - N4_X - N4_WQ - 2 * N4_WKV; }
    float4 v = src[off];
    v.x = f2tf(v.x); v.y = f2tf(v.y); v.z = f2tf(v.z); v.w = f2tf(v.w);
    dst[off] = v;
}

// ---------------------------------------------------------------------------
// tf32 GEMM body: C = A @ W^T + bias. Padded smem + cp.async 2-stage pipeline.
// Inputs pre-rounded to tf32, so HW truncation at the mma is exact RNA.
// ROUND_OUT: round the epilogue result to tf32 (for tensors feeding later mmas).
// ---------------------------------------------------------------------------
#define TBM 128
#define TBN 128
#define TBK 32
#define TPAD 36
#define GEMM_SMEM (2 * 2 * TBM * TPAD * 4)   // 73728 bytes

template<bool ROUND_OUT>
__device__ __forceinline__
void gemm_body(const float* __restrict__ A, const float* __restrict__ W,
               const float* __restrict__ bias, float* __restrict__ C,
               int N, int K, int bm, int bn, float* As, float* Ws)
{
    const int tid   = threadIdx.x;
    const int lane  = tid & 31;
    const int wid   = tid >> 5;
    const int gID   = lane >> 2;
    const int tig   = lane & 3;
    const int wmSel = wid & 1;
    const int wnSel = wid >> 1;
    const unsigned asb = (unsigned)__cvta_generic_to_shared(As);
    const unsigned wsb = (unsigned)__cvta_generic_to_shared(Ws);

    float acc[4][4][4];
#pragma unroll
    for (int mi = 0; mi < 4; mi++)
#pragma unroll
        for (int ni = 0; ni < 4; ni++)
#pragma unroll
            for (int j = 0; j < 4; j++) acc[mi][ni][j] = 0.f;

    const int NT = K / TBK;

#pragma unroll
    for (int it = 0; it < 4; it++) {
        int idx = tid + it * 256, row = idx >> 3, c4 = (idx & 7) << 2;
        cp16(asb + (unsigned)((row * TPAD + c4) << 2), A + (size_t)(bm + row) * K + c4);
        cp16(wsb + (unsigned)((row * TPAD + c4) << 2), W + (size_t)(bn + row) * K + c4);
    }
    asm volatile("cp.async.commit_group;\n");

    for (int kt = 0; kt < NT; kt++) {
        int buf = kt & 1;
        if (kt + 1 < NT) {
            int k0n = (kt + 1) * TBK, bufn = (kt + 1) & 1;
#pragma unroll
            for (int it = 0; it < 4; it++) {
                int idx = tid + it * 256, row = idx >> 3, c4 = (idx & 7) << 2;
                cp16(asb + (unsigned)(((bufn * TBM + row) * TPAD + c4) << 2),
                     A + (size_t)(bm + row) * K + k0n + c4);
                cp16(wsb + (unsigned)(((bufn * TBM + row) * TPAD + c4) << 2),
                     W + (size_t)(bn + row) * K + k0n + c4);
            }
            asm volatile("cp.async.commit_group;\n");
            asm volatile("cp.async.wait_group 1;\n");
        } else {
            asm volatile("cp.async.wait_group 0;\n");
        }
        __syncthreads();

        const float* Ab = As + buf * TBM * TPAD;
        const float* Wb = Ws + buf * TBM * TPAD;
#pragma unroll
        for (int ks = 0; ks < 4; ks++) {
            unsigned af[4][4], bf[4][2];
#pragma unroll
            for (int mi = 0; mi < 4; mi++) {
                int r = wmSel * 64 + mi * 16 + gID;
                af[mi][0] = __float_as_uint(Ab[r * TPAD + ks * 8 + tig]);
                af[mi][1] = __float_as_uint(Ab[(r + 8) * TPAD + ks * 8 + tig]);
                af[mi][2] = __float_as_uint(Ab[r * TPAD + ks * 8 + tig + 4]);
                af[mi][3] = __float_as_uint(Ab[(r + 8) * TPAD + ks * 8 + tig + 4]);
            }
#pragma unroll
            for (int ni = 0; ni < 4; ni++) {
                int c = wnSel * 32 + ni * 8 + gID;
                bf[ni][0] = __float_as_uint(Wb[c * TPAD + ks * 8 + tig]);
                bf[ni][1] = __float_as_uint(Wb[c * TPAD + ks * 8 + tig + 4]);
            }
#pragma unroll
            for (int mi = 0; mi < 4; mi++)
#pragma unroll
                for (int ni = 0; ni < 4; ni++)
                    mma8(acc[mi][ni], af[mi], bf[ni]);
        }
        __syncthreads();
    }

    const int wm = wmSel * 64;
    const int wn = wnSel * 32;
#pragma unroll
    for (int mi = 0; mi < 4; mi++) {
        int r = bm + wm + mi * 16 + gID;
#pragma unroll
        for (int ni = 0; ni < 4; ni++) {
            int c = bn + wn + ni * 8 + 2 * tig;
            float2 bv = *(const float2*)(bias + c);
            float o0 = acc[mi][ni][0] + bv.x, o1 = acc[mi][ni][1] + bv.y;
            float o2 = acc[mi][ni][2] + bv.x, o3 = acc[mi][ni][3] + bv.y;
            if (ROUND_OUT) { o0 = f2tf(o0); o1 = f2tf(o1); o2 = f2tf(o2); o3 = f2tf(o3); }
            *(float2*)(C + (size_t)r * N + c)       = make_float2(o0, o1);
            *(float2*)(C + (size_t)(r + 8) * N + c) = make_float2(o2, o3);
        }
    }
}

// Fused QKV projection: outputs pre-rounded to tf32 for the attention mmas.
__global__ __launch_bounds__(256, 2)
void qkv_tf32(const float* __restrict__ x,
              const float* __restrict__ Wq, const float* __restrict__ bq,
              const float* __restrict__ Wk, const float* __restrict__ bk,
              const float* __restrict__ Wv, const float* __restrict__ bv,
              float* __restrict__ qp, float* __restrict__ kp, float* __restrict__ vp)
{
    extern __shared__ float dsm[];
    float* As = dsm;
    float* Ws = dsm + 2 * TBM * TPAD;
    int bx = blockIdx.x;
    const float *W, *bias; float* C; int N, bn;
    if (bx < 16)      { W = Wq; bias = bq; C = qp; N = QINNER;  bn = bx * 128; }
    else if (bx < 20) { W = Wk; bias = bk; C = kp; N = KVINNER; bn = (bx - 16) * 128; }
    else              { W = Wv; bias = bv; C = vp; N = KVINNER; bn = (bx - 20) * 128; }
    gemm_body<true>(x, W, bias, C, N, DMODEL, blockIdx.y * TBM, bn, As, Ws);
}

__global__ __launch_bounds__(256, 2)
void oproj_tf32(const float* __restrict__ A, const float* __restrict__ Wo,
                const float* __restrict__ bo, float* __restrict__ C)
{
    extern __shared__ float dsm[];
    float* As = dsm;
    float* Ws = dsm + 2 * TBM * TPAD;
    gemm_body<false>(A, Wo, bo, C, DMODEL, QINNER, blockIdx.y * TBM, blockIdx.x * TBN, As, Ws);
}

// ---------------------------------------------------------------------------
// tf32 flash attention, fragment-major K/V smem.
// ABQ=64 q rows/CTA, 4 warps (128 threads) -> 2 CTAs/SM: fill+barriers of one
// CTA overlap the other's mma; 1024 CTAs kill the tail wave.
// Inputs g_q/g_k/g_v are pre-rounded tf32 -> no cvt in fill / qa load.
// ---------------------------------------------------------------------------
#define ABQ  64
#define ABK  64
#define ATHR 128
#define PPAD 68
#define KF_U4 (16 * 4 * 32)     // 2048 uint4 = 32KB
#define VF_U4 (8 * 8 * 32)      // 2048 uint4 = 32KB
#define SMEM_ATTN ((KF_U4 + VF_U4) * 16 + ABQ * PPAD * (int)sizeof(float))

__global__ __launch_bounds__(ATHR, 2)
void attn_tf32(const int* __restrict__ mask)
{
    extern __shared__ float sm[];
    uint4* Kf = (uint4*)sm;
    uint4* Vf = Kf + KF_U4;
    float* Kff = (float*)Kf;
    float* Vff = (float*)Vf;
    float* Ps  = (float*)(Vf + VF_U4);   // [64][PPAD]

    const int tid  = threadIdx.x;
    const int lane = tid & 31;
    const int wid  = tid >> 5;        // 0..3
    const int gID  = lane >> 2;
    const int tig  = lane & 3;
    const int q0   = blockIdx.x * ABQ;
    const int bh   = blockIdx.y;
    const int b    = bh >> 4;
    const int h    = bh & 15;
    const int kh   = h >> 2;
    const float scale = 0.08838834764831845f;   // 1/sqrt(128)

    // ---- Q fragments in registers (pre-rounded tf32: raw bit loads) ----
    const int qr0 = q0 + wid * 16 + gID;
    const unsigned* qb0 = (const unsigned*)(g_q + (size_t)(b * SEQ + qr0) * QINNER + h * DHEAD);
    const unsigned* qb1 = qb0 + 8 * QINNER;
    unsigned qa[16][4];
#pragma unroll
    for (int ks = 0; ks < 16; ks++) {
        qa[ks][0] = qb0[ks * 8 + tig];
        qa[ks][1] = qb1[ks * 8 + tig];
        qa[ks][2] = qb0[ks * 8 + tig + 4];
        qa[ks][3] = qb1[ks * 8 + tig + 4];
    }

    float o[16][4];
#pragma unroll
    for (int n = 0; n < 16; n++)
#pragma unroll
        for (int j = 0; j < 4; j++) o[n][j] = 0.f;
    float m0 = -1e30f, m1 = -1e30f, l0 = 0.f, l1 = 0.f;

    const int* mrow0 = mask + (size_t)b * SEQ * SEQ + (size_t)qr0 * SEQ;
    const int* mrow1 = mrow0 + 8 * SEQ;

    float* prow0 = Ps + (wid * 16 + gID) * PPAD;
    float* prow1 = prow0 + 8 * PPAD;

    const int f_ks  = lane >> 1;
    const int f_half = lane & 1;
    const int f_ni  = lane >> 1;
    const int f_nip = lane >> 2;

    for (int k0 = 0; k0 < SEQ; k0 += ABK) {
        __syncthreads();
        // ---- fill K/V fragment-major tiles (values already tf32) ----
#pragma unroll
        for (int it = 0; it < 16; it++) {
            int r = wid + it * 4;                 // key row 0..63
            size_t goff = (size_t)(b * SEQ + k0 + r) * KVINNER + kh * DHEAD + lane * 4;
            {
                int ni  = r >> 3, gK = r & 7, nip = ni >> 1;
                int kbase = ((f_ks * 4 + nip) * 32) * 4 + f_half + ((ni & 1) << 1);
                int sw = f_ks & 7;
                float4 kv = *(const float4*)(g_k + goff);
                Kff[kbase + (((gK << 2) | 0) ^ sw) * 4] = kv.x;
                Kff[kbase + (((gK << 2) | 1) ^ sw) * 4] = kv.y;
                Kff[kbase + (((gK << 2) | 2) ^ sw) * 4] = kv.z;
                Kff[kbase + (((gK << 2) | 3) ^ sw) * 4] = kv.w;
            }
            {
                int ks2 = r >> 3, tigv = r & 3, halfv = (r >> 2) & 1;
                int vbase = ((ks2 * 8 + f_nip) * 32) * 4 + halfv + ((f_ni & 1) << 1);
                int sw = f_nip & 7;
                int g0 = (lane & 1) << 2;
                float4 vv = *(const float4*)(g_v + goff);
                Vff[vbase + ((((g0 | 0) << 2) | tigv) ^ sw) * 4] = vv.x;
                Vff[vbase + ((((g0 | 1) << 2) | tigv) ^ sw) * 4] = vv.y;
                Vff[vbase + ((((g0 | 2) << 2) | tigv) ^ sw) * 4] = vv.z;
                Vff[vbase + ((((g0 | 3) << 2) | tigv) ^ sw) * 4] = vv.w;
            }
        }
        __syncthreads();

        // ---- S = Q @ K^T ----
        float s[8][4];
#pragma unroll
        for (int ni = 0; ni < 8; ni++)
#pragma unroll
            for (int j = 0; j < 4; j++) s[ni][j] = 0.f;

#pragma unroll
        for (int ks = 0; ks < 16; ks++) {
            int lsw = lane ^ (ks & 7);
#pragma unroll
            for (int nip = 0; nip < 4; nip++) {
                uint4 kf = Kf[(ks * 4 + nip) * 32 + lsw];
                unsigned bfe[2] = {kf.x, kf.y};
                unsigned bfo[2] = {kf.z, kf.w};
                mma8(s[2 * nip],     qa[ks], bfe);
                mma8(s[2 * nip + 1], qa[ks], bfo);
            }
        }

        // ---- scale + mask + online softmax ----
        float nm0 = m0, nm1 = m1;
#pragma unroll
        for (int ni = 0; ni < 8; ni++) {
            int cc = k0 + ni * 8 + 2 * tig;
            int2 mm0 = *(const int2*)(mrow0 + cc);
            int2 mm1 = *(const int2*)(mrow1 + cc);
            s[ni][0] = mm0.x ? s[ni][0] * scale : -1e30f;
            s[ni][1] = mm0.y ? s[ni][1] * scale : -1e30f;
            s[ni][2] = mm1.x ? s[ni][2] * scale : -1e30f;
            s[ni][3] = mm1.y ? s[ni][3] * scale : -1e30f;
            nm0 = fmaxf(nm0, fmaxf(s[ni][0], s[ni][1]));
            nm1 = fmaxf(nm1, fmaxf(s[ni][2], s[ni][3]));
        }
        nm0 = fmaxf(nm0, __shfl_xor_sync(0xffffffffu, nm0, 1));
        nm0 = fmaxf(nm0, __shfl_xor_sync(0xffffffffu, nm0, 2));
        nm1 = fmaxf(nm1, __shfl_xor_sync(0xffffffffu, nm1, 1));
        nm1 = fmaxf(nm1, __shfl_xor_sync(0xffffffffu, nm1, 2));

        float corr0 = __expf(m0 - nm0);
        float corr1 = __expf(m1 - nm1);
        m0 = nm0; m1 = nm1;

        float rs0 = 0.f, rs1 = 0.f;
#pragma unroll
        for (int ni = 0; ni < 8; ni++) {
            s[ni][0] = (s[ni][0] > -1e29f) ? __expf(s[ni][0] - m0) : 0.f;
            s[ni][1] = (s[ni][1] > -1e29f) ? __expf(s[ni][1] - m0) : 0.f;
            s[ni][2] = (s[ni][2] > -1e29f) ? __expf(s[ni][2] - m1) : 0.f;
            s[ni][3] = (s[ni][3] > -1e29f) ? __expf(s[ni][3] - m1) : 0.f;
            rs0 += s[ni][0] + s[ni][1];
            rs1 += s[ni][2] + s[ni][3];
        }
        rs0 += __shfl_xor_sync(0xffffffffu, rs0, 1);
        rs0 += __shfl_xor_sync(0xffffffffu, rs0, 2);
        rs1 += __shfl_xor_sync(0xffffffffu, rs1, 1);
        rs1 += __shfl_xor_sync(0xffffffffu, rs1, 2);
        l0 = l0 * corr0 + rs0;
        l1 = l1 * corr1 + rs1;

#pragma unroll
        for (int n = 0; n < 16; n++) {
            o[n][0] *= corr0; o[n][1] *= corr0;
            o[n][2] *= corr1; o[n][3] *= corr1;
        }

        // ---- stash P (tf32) in warp-private smem rows ----
#pragma unroll
        for (int ni = 0; ni < 8; ni++) {
            *(float2*)(prow0 + ni * 8 + 2 * tig) = make_float2(f2tf(s[ni][0]), f2tf(s[ni][1]));
            *(float2*)(prow1 + ni * 8 + 2 * tig) = make_float2(f2tf(s[ni][2]), f2tf(s[ni][3]));
        }
        __syncwarp();

        // ---- O += P @ V ----
#pragma unroll
        for (int ks2 = 0; ks2 < 8; ks2++) {
            unsigned pa[4];
            pa[0] = __float_as_uint(prow0[ks2 * 8 + tig]);
            pa[1] = __float_as_uint(prow1[ks2 * 8 + tig]);
            pa[2] = __float_as_uint(prow0[ks2 * 8 + tig + 4]);
            pa[3] = __float_as_uint(prow1[ks2 * 8 + tig + 4]);
#pragma unroll
            for (int nip = 0; nip < 8; nip++) {
                uint4 vf = Vf[(ks2 * 8 + nip) * 32 + (lane ^ nip)];
                unsigned bfe[2] = {vf.x, vf.y};
                unsigned bfo[2] = {vf.z, vf.w};
                mma8(o[2 * nip],     pa, bfe);
                mma8(o[2 * nip + 1], pa, bfo);
            }
        }
    }

    // ---- normalize + store [b,s,h,d], pre-rounded to tf32 for O-proj ----
    float inv0 = (l0 > 0.f) ? (1.f / l0) : 0.f;
    float inv1 = (l1 > 0.f) ? (1.f / l1) : 0.f;
    float* ob0 = g_att + (size_t)(b * SEQ + qr0) * QINNER + h * DHEAD;
    float* ob1 = ob0 + 8 * QINNER;
#pragma unroll
    for (int ni = 0; ni < 16; ni++) {
        *(float2*)(ob0 + ni * 8 + 2 * tig) =
            make_float2(f2tf(o[ni][0] * inv0), f2tf(o[ni][1] * inv0));
        *(float2*)(ob1 + ni * 8 + 2 * tig) =
            make_float2(f2tf(o[ni][2] * inv1), f2tf(o[ni][3] * inv1));
    }
}

// ---------------------------------------------------------------------------
// Launch
// ---------------------------------------------------------------------------
extern "C" void kernel_launch(void* const* d_in, const int* in_sizes, int n_in,
                              void* d_out, int out_size)
{
    const float* x    = (const float*)d_in[0];
    const int*   mask = (const int*)  d_in[1];
    const float* Wq   = (const float*)d_in[2];
    const float* bq   = (const float*)d_in[3];
    const float* Wk   = (const float*)d_in[4];
    const float* bk   = (const float*)d_in[5];
    const float* Wv   = (const float*)d_in[6];
    const float* bv   = (const float*)d_in[7];
    const float* Wo   = (const float*)d_in[8];
    const float* bo   = (const float*)d_in[9];
    float* out = (float*)d_out;

    float *q, *k, *v, *att, *x19, *wq19, *wk19, *wv19, *wo19;
    cudaGetSymbolAddress((void**)&q,    g_q);
    cudaGetSymbolAddress((void**)&k,    g_k);
    cudaGetSymbolAddress((void**)&v,    g_v);
    cudaGetSymbolAddress((void**)&att,  g_att);
    cudaGetSymbolAddress((void**)&x19,  g_x19);
    cudaGetSymbolAddress((void**)&wq19, g_wq19);
    cudaGetSymbolAddress((void**)&wk19, g_wk19);
    cudaGetSymbolAddress((void**)&wv19, g_wv19);
    cudaGetSymbolAddress((void**)&wo19, g_wo19);

    cudaFuncSetAttribute(attn_tf32,  cudaFuncAttributeMaxDynamicSharedMemorySize, SMEM_ATTN);
    cudaFuncSetAttribute(qkv_tf32,   cudaFuncAttributeMaxDynamicSharedMemorySize, GEMM_SMEM);
    cudaFuncSetAttribute(oproj_tf32, cudaFuncAttributeMaxDynamicSharedMemorySize, GEMM_SMEM);

    dim3 thr(256);
    round_all<<<(N4_ALL + 255) / 256, thr>>>(
        (const float4*)x,  (float4*)x19,
        (const float4*)Wq, (float4*)wq19,
        (const float4*)Wk, (float4*)wk19,
        (const float4*)Wv, (float4*)wv19,
        (const float4*)Wo, (float4*)wo19);

    qkv_tf32<<<dim3(24, MROWS / TBM), thr, GEMM_SMEM>>>(x19, wq19, bq, wk19, bk, wv19, bv, q, k, v);
    attn_tf32<<<dim3(SEQ / ABQ, BB * NHEAD), dim3(ATHR), SMEM_ATTN>>>(mask);
    oproj_tf32<<<dim3(DMODEL / TBN, MROWS / TBM), thr, GEMM_SMEM>>>(att, wo19, bo, out);
}

// round 11
// speedup vs baseline: 1.0985x; 1.0691x over previous
#include <cuda_runtime.h>
#include <math.h>

// ---------------------------------------------------------------------------
// Problem constants
// ---------------------------------------------------------------------------
#define BB      2
#define SEQ     2048
#define DMODEL  2048
#define NHEAD   16
#define NKV     4
#define DHEAD   128
#define QINNER  (NHEAD * DHEAD)    // 2048
#define KVINNER (NKV * DHEAD)      // 512
#define NREP    (NHEAD / NKV)      // 4
#define MROWS   (BB * SEQ)         // 4096
#define NTILE   (SEQ / 64)         // 32 KV tiles per (b,kh)

// Scratch (allocation-free rule: device globals)
__device__ float g_q[MROWS * QINNER];     // tf32-rounded by qkv epilogue
__device__ float g_k[MROWS * KVINNER];    // tf32-rounded
__device__ float g_v[MROWS * KVINNER];    // tf32-rounded
__device__ float g_att[MROWS * QINNER];   // tf32-rounded by attn epilogue
// K/V in attention fragment-major swizzled layout: [b][kh][tile] x 8192 floats
__device__ float g_kf[BB * NKV * NTILE * 8192];
__device__ float g_vf[BB * NKV * NTILE * 8192];
// tf32-pre-rounded copies of GEMM inputs (HW truncation becomes exact RNA)
__device__ float g_x19[MROWS * DMODEL];
__device__ float g_wq19[QINNER * DMODEL];
__device__ float g_wk19[KVINNER * DMODEL];
__device__ float g_wv19[KVINNER * DMODEL];
__device__ float g_wo19[DMODEL * QINNER];

// ---------------------------------------------------------------------------
// tf32 helpers
// ---------------------------------------------------------------------------
__device__ __forceinline__ float f2tf(float x) {
    unsigned y;
    asm("cvt.rna.tf32.f32 %0, %1;" : "=r"(y) : "f"(x));
    return __uint_as_float(y);
}

// D += A(16x8) * B(8x8), tf32 inputs, fp32 accum
__device__ __forceinline__ void mma8(float* d, const unsigned* a, const unsigned* b) {
    asm("mma.sync.aligned.m16n8k8.row.col.f32.tf32.tf32.f32 "
        "{%0,%1,%2,%3},{%4,%5,%6,%7},{%8,%9},{%0,%1,%2,%3};"
        : "+f"(d[0]), "+f"(d[1]), "+f"(d[2]), "+f"(d[3])
        : "r"(a[0]), "r"(a[1]), "r"(a[2]), "r"(a[3]), "r"(b[0]), "r"(b[1]));
}

__device__ __forceinline__ void cp16(unsigned s, const void* g) {
    asm volatile("cp.async.cg.shared.global [%0], [%1], 16;\n" :: "r"(s), "l"(g));
}

// ---------------------------------------------------------------------------
// Fused RNA round-to-tf32 of all five GEMM inputs (one launch)
// ---------------------------------------------------------------------------
#define N4_X   (MROWS * DMODEL / 4)
#define N4_WQ  (QINNER * DMODEL / 4)
#define N4_WKV (KVINNER * DMODEL / 4)
#define N4_WO  (DMODEL * QINNER / 4)
#define N4_ALL (N4_X + N4_WQ + 2 * N4_WKV + N4_WO)

__global__ __launch_bounds__(256)
void round_all(const float4* __restrict__ x,  float4* __restrict__ xo,
               const float4* __restrict__ wq, float4* __restrict__ wqo,
               const float4* __restrict__ wk, float4* __restrict__ wko,
               const float4* __restrict__ wv, float4* __restrict__ wvo,
               const float4* __restrict__ wo, float4* __restrict__ woo)
{
    int i = blockIdx.x * blockDim.x + threadIdx.x;
    if (i >= N4_ALL) return;
    const float4* src; float4* dst; int off;
    if (i < N4_X)                            { src = x;  dst = xo;  off = i; }
    else if (i < N4_X + N4_WQ)               { src = wq; dst = wqo; off = i - N4_X; }
    else if (i < N4_X + N4_WQ + N4_WKV)      { src = wk; dst = wko; off = i - N4_X - N4_WQ; }
    else if (i < N4_X + N4_WQ + 2 * N4_WKV)  { src = wv; dst = wvo; off = i - N4_X - N4_WQ - N4_WKV; }
    else                                     { src = wo; dst = woo; off = i - N4_X - N4_WQ - 2 * N4_WKV; }
    float4 v = src[off];
    v.x = f2tf(v.x); v.y = f2tf(v.y); v.z = f2tf(v.z); v.w = f2tf(v.w);
    dst[off] = v;
}

// ---------------------------------------------------------------------------
// kv_pack: permute tf32-rounded K/V into the attention fragment-major
// swizzled layout (pure bit movement; numerics unchanged).
// thread -> (b, kh, s, lane); lane covers 4 consecutive d (coalesced reads).
// ---------------------------------------------------------------------------
__global__ __launch_bounds__(256)
void kv_pack()
{
    int gidx  = blockIdx.x * 256 + threadIdx.x;     // 0 .. 524287
    int lane  = gidx & 31;                          // d-group (d = lane*4)
    int s_lin = gidx >> 5;                          // 0 .. 16383
    int s  = s_lin & (SEQ - 1);
    int bk = s_lin >> 11;                           // 0..7
    int b  = bk >> 2;
    int kh = bk & 3;

    size_t goff = (size_t)(b * SEQ + s) * KVINNER + kh * DHEAD + lane * 4;
    float4 kv = *(const float4*)(g_k + goff);
    float4 vv = *(const float4*)(g_v + goff);

    int r = s & 63;
    int t = s >> 6;
    size_t blk = ((size_t)(b * NKV + kh) * NTILE + t) << 13;   // * 8192 floats
    float* kdst = g_kf + blk;
    float* vdst = g_vf + blk;

    const int f_ks  = lane >> 1;
    const int f_half = lane & 1;
    const int f_ni  = lane >> 1;
    const int f_nip = lane >> 2;

    // K element (r, d=4*lane+j)
    {
        int ni = r >> 3, gK = r & 7, nip = ni >> 1;
        int kbase = ((f_ks * 4 + nip) * 32) * 4 + f_half + ((ni & 1) << 1);
        int sw = f_ks & 7;
        kdst[kbase + (((gK << 2) | 0) ^ sw) * 4] = kv.x;
        kdst[kbase + (((gK << 2) | 1) ^ sw) * 4] = kv.y;
        kdst[kbase + (((gK << 2) | 2) ^ sw) * 4] = kv.z;
        kdst[kbase + (((gK << 2) | 3) ^ sw) * 4] = kv.w;
    }
    // V element
    {
        int ks2 = r >> 3, tigv = r & 3, halfv = (r >> 2) & 1;
        int vbase = ((ks2 * 8 + f_nip) * 32) * 4 + halfv + ((f_ni & 1) << 1);
        int sw = f_nip & 7;
        int g0 = (lane & 1) << 2;
        vdst[vbase + ((((g0 | 0) << 2) | tigv) ^ sw) * 4] = vv.x;
        vdst[vbase + ((((g0 | 1) << 2) | tigv) ^ sw) * 4] = vv.y;
        vdst[vbase + ((((g0 | 2) << 2) | tigv) ^ sw) * 4] = vv.z;
        vdst[vbase + ((((g0 | 3) << 2) | tigv) ^ sw) * 4] = vv.w;
    }
}

// ---------------------------------------------------------------------------
// tf32 GEMM body: C = A @ W^T + bias. Padded smem + cp.async 2-stage pipeline.
// ---------------------------------------------------------------------------
#define TBM 128
#define TBN 128
#define TBK 32
#define TPAD 36
#define GEMM_SMEM (2 * 2 * TBM * TPAD * 4)   // 73728 bytes

template<bool ROUND_OUT>
__device__ __forceinline__
void gemm_body(const float* __restrict__ A, const float* __restrict__ W,
               const float* __restrict__ bias, float* __restrict__ C,
               int N, int K, int bm, int bn, float* As, float* Ws)
{
    const int tid   = threadIdx.x;
    const int lane  = tid & 31;
    const int wid   = tid >> 5;
    const int gID   = lane >> 2;
    const int tig   = lane & 3;
    const int wmSel = wid & 1;
    const int wnSel = wid >> 1;
    const unsigned asb = (unsigned)__cvta_generic_to_shared(As);
    const unsigned wsb = (unsigned)__cvta_generic_to_shared(Ws);

    float acc[4][4][4];
#pragma unroll
    for (int mi = 0; mi < 4; mi++)
#pragma unroll
        for (int ni = 0; ni < 4; ni++)
#pragma unroll
            for (int j = 0; j < 4; j++) acc[mi][ni][j] = 0.f;

    const int NT = K / TBK;

#pragma unroll
    for (int it = 0; it < 4; it++) {
        int idx = tid + it * 256, row = idx >> 3, c4 = (idx & 7) << 2;
        cp16(asb + (unsigned)((row * TPAD + c4) << 2), A + (size_t)(bm + row) * K + c4);
        cp16(wsb + (unsigned)((row * TPAD + c4) << 2), W + (size_t)(bn + row) * K + c4);
    }
    asm volatile("cp.async.commit_group;\n");

    for (int kt = 0; kt < NT; kt++) {
        int buf = kt & 1;
        if (kt + 1 < NT) {
            int k0n = (kt + 1) * TBK, bufn = (kt + 1) & 1;
#pragma unroll
            for (int it = 0; it < 4; it++) {
                int idx = tid + it * 256, row = idx >> 3, c4 = (idx & 7) << 2;
                cp16(asb + (unsigned)(((bufn * TBM + row) * TPAD + c4) << 2),
                     A + (size_t)(bm + row) * K + k0n + c4);
                cp16(wsb + (unsigned)(((bufn * TBM + row) * TPAD + c4) << 2),
                     W + (size_t)(bn + row) * K + k0n + c4);
            }
            asm volatile("cp.async.commit_group;\n");
            asm volatile("cp.async.wait_group 1;\n");
        } else {
            asm volatile("cp.async.wait_group 0;\n");
        }
        __syncthreads();

        const float* Ab = As + buf * TBM * TPAD;
        const float* Wb = Ws + buf * TBM * TPAD;
#pragma unroll
        for (int ks = 0; ks < 4; ks++) {
            unsigned af[4][4], bf[4][2];
#pragma unroll
            for (int mi = 0; mi < 4; mi++) {
                int r = wmSel * 64 + mi * 16 + gID;
                af[mi][0] = __float_as_uint(Ab[r * TPAD + ks * 8 + tig]);
                af[mi][1] = __float_as_uint(Ab[(r + 8) * TPAD + ks * 8 + tig]);
                af[mi][2] = __float_as_uint(Ab[r * TPAD + ks * 8 + tig + 4]);
                af[mi][3] = __float_as_uint(Ab[(r + 8) * TPAD + ks * 8 + tig + 4]);
            }
#pragma unroll
            for (int ni = 0; ni < 4; ni++) {
                int c = wnSel * 32 + ni * 8 + gID;
                bf[ni][0] = __float_as_uint(Wb[c * TPAD + ks * 8 + tig]);
                bf[ni][1] = __float_as_uint(Wb[c * TPAD + ks * 8 + tig + 4]);
            }
#pragma unroll
            for (int mi = 0; mi < 4; mi++)
#pragma unroll
                for (int ni = 0; ni < 4; ni++)
                    mma8(acc[mi][ni], af[mi], bf[ni]);
        }
        __syncthreads();
    }

    const int wm = wmSel * 64;
    const int wn = wnSel * 32;
#pragma unroll
    for (int mi = 0; mi < 4; mi++) {
        int r = bm + wm + mi * 16 + gID;
#pragma unroll
        for (int ni = 0; ni < 4; ni++) {
            int c = bn + wn + ni * 8 + 2 * tig;
            float2 bv = *(const float2*)(bias + c);
            float o0 = acc[mi][ni][0] + bv.x, o1 = acc[mi][ni][1] + bv.y;
            float o2 = acc[mi][ni][2] + bv.x, o3 = acc[mi][ni][3] + bv.y;
            if (ROUND_OUT) { o0 = f2tf(o0); o1 = f2tf(o1); o2 = f2tf(o2); o3 = f2tf(o3); }
            *(float2*)(C + (size_t)r * N + c)       = make_float2(o0, o1);
            *(float2*)(C + (size_t)(r + 8) * N + c) = make_float2(o2, o3);
        }
    }
}

__global__ __launch_bounds__(256, 2)
void qkv_tf32(const float* __restrict__ x,
              const float* __restrict__ Wq, const float* __restrict__ bq,
              const float* __restrict__ Wk, const float* __restrict__ bk,
              const float* __restrict__ Wv, const float* __restrict__ bv,
              float* __restrict__ qp, float* __restrict__ kp, float* __restrict__ vp)
{
    extern __shared__ float dsm[];
    float* As = dsm;
    float* Ws = dsm + 2 * TBM * TPAD;
    int bx = blockIdx.x;
    const float *W, *bias; float* C; int N, bn;
    if (bx < 16)      { W = Wq; bias = bq; C = qp; N = QINNER;  bn = bx * 128; }
    else if (bx < 20) { W = Wk; bias = bk; C = kp; N = KVINNER; bn = (bx - 16) * 128; }
    else              { W = Wv; bias = bv; C = vp; N = KVINNER; bn = (bx - 20) * 128; }
    gemm_body<true>(x, W, bias, C, N, DMODEL, blockIdx.y * TBM, bn, As, Ws);
}

__global__ __launch_bounds__(256, 2)
void oproj_tf32(const float* __restrict__ A, const float* __restrict__ Wo,
                const float* __restrict__ bo, float* __restrict__ C)
{
    extern __shared__ float dsm[];
    float* As = dsm;
    float* Ws = dsm + 2 * TBM * TPAD;
    gemm_body<false>(A, Wo, bo, C, DMODEL, QINNER, blockIdx.y * TBM, blockIdx.x * TBN, As, Ws);
}

// ---------------------------------------------------------------------------
// tf32 flash attention. K/V tiles arrive pre-packed in fragment-major layout
// (g_kf/g_vf) -> fill is pure contiguous cp.async (no STS, no index ALU).
// ABQ=64, 4 warps, 2 CTAs/SM.
// ---------------------------------------------------------------------------
#define ABQ  64
#define ABK  64
#define ATHR 128
#define PPAD 68
#define KF_U4 (16 * 4 * 32)     // 2048 uint4 = 32KB
#define VF_U4 (8 * 8 * 32)      // 2048 uint4 = 32KB
#define SMEM_ATTN ((KF_U4 + VF_U4) * 16 + ABQ * PPAD * (int)sizeof(float))

__global__ __launch_bounds__(ATHR, 2)
void attn_tf32(const int* __restrict__ mask)
{
    extern __shared__ float sm[];
    uint4* Kf = (uint4*)sm;
    uint4* Vf = Kf + KF_U4;
    float* Ps = (float*)(Vf + VF_U4);   // [64][PPAD]

    const int tid  = threadIdx.x;
    const int lane = tid & 31;
    const int wid  = tid >> 5;        // 0..3
    const int gID  = lane >> 2;
    const int tig  = lane & 3;
    const int q0   = blockIdx.x * ABQ;
    const int bh   = blockIdx.y;
    const int b    = bh >> 4;
    const int h    = bh & 15;
    const int kh   = h >> 2;
    const float scale = 0.08838834764831845f;   // 1/sqrt(128)

    const unsigned kfs = (unsigned)__cvta_generic_to_shared(Kf);
    const unsigned vfs = (unsigned)__cvta_generic_to_shared(Vf);
    const float* kblk0 = g_kf + ((size_t)(b * NKV + kh) * NTILE << 13);
    const float* vblk0 = g_vf + ((size_t)(b * NKV + kh) * NTILE << 13);

    // ---- Q fragments in registers (pre-rounded tf32: raw bit loads) ----
    const int qr0 = q0 + wid * 16 + gID;
    const unsigned* qb0 = (const unsigned*)(g_q + (size_t)(b * SEQ + qr0) * QINNER + h * DHEAD);
    const unsigned* qb1 = qb0 + 8 * QINNER;
    unsigned qa[16][4];
#pragma unroll
    for (int ks = 0; ks < 16; ks++) {
        qa[ks][0] = qb0[ks * 8 + tig];
        qa[ks][1] = qb1[ks * 8 + tig];
        qa[ks][2] = qb0[ks * 8 + tig + 4];
        qa[ks][3] = qb1[ks * 8 + tig + 4];
    }

    float o[16][4];
#pragma unroll
    for (int n = 0; n < 16; n++)
#pragma unroll
        for (int j = 0; j < 4; j++) o[n][j] = 0.f;
    float m0 = -1e30f, m1 = -1e30f, l0 = 0.f, l1 = 0.f;

    const int* mrow0 = mask + (size_t)b * SEQ * SEQ + (size_t)qr0 * SEQ;
    const int* mrow1 = mrow0 + 8 * SEQ;

    float* prow0 = Ps + (wid * 16 + gID) * PPAD;
    float* prow1 = prow0 + 8 * PPAD;

    for (int k0 = 0; k0 < SEQ; k0 += ABK) {
        __syncthreads();
        // ---- fill K/V tiles: contiguous cp.async from pre-packed layout ----
        {
            const float* kb = kblk0 + ((size_t)(k0 >> 6) << 13);
            const float* vb = vblk0 + ((size_t)(k0 >> 6) << 13);
#pragma unroll
            for (int it = 0; it < 16; it++) {
                int u = tid + it * ATHR;                // 0..2047 uint4
                cp16(kfs + u * 16, kb + u * 4);
                cp16(vfs + u * 16, vb + u * 4);
            }
            asm volatile("cp.async.commit_group;\n");
            asm volatile("cp.async.wait_group 0;\n");
        }
        __syncthreads();

        // ---- S = Q @ K^T ----
        float s[8][4];
#pragma unroll
        for (int ni = 0; ni < 8; ni++)
#pragma unroll
            for (int j = 0; j < 4; j++) s[ni][j] = 0.f;

#pragma unroll
        for (int ks = 0; ks < 16; ks++) {
            int lsw = lane ^ (ks & 7);
#pragma unroll
            for (int nip = 0; nip < 4; nip++) {
                uint4 kf = Kf[(ks * 4 + nip) * 32 + lsw];
                unsigned bfe[2] = {kf.x, kf.y};
                unsigned bfo[2] = {kf.z, kf.w};
                mma8(s[2 * nip],     qa[ks], bfe);
                mma8(s[2 * nip + 1], qa[ks], bfo);
            }
        }

        // ---- scale + mask + online softmax ----
        float nm0 = m0, nm1 = m1;
#pragma unroll
        for (int ni = 0; ni < 8; ni++) {
            int cc = k0 + ni * 8 + 2 * tig;
            int2 mm0 = *(const int2*)(mrow0 + cc);
            int2 mm1 = *(const int2*)(mrow1 + cc);
            s[ni][0] = mm0.x ? s[ni][0] * scale : -1e30f;
            s[ni][1] = mm0.y ? s[ni][1] * scale : -1e30f;
            s[ni][2] = mm1.x ? s[ni][2] * scale : -1e30f;
            s[ni][3] = mm1.y ? s[ni][3] * scale : -1e30f;
            nm0 = fmaxf(nm0, fmaxf(s[ni][0], s[ni][1]));
            nm1 = fmaxf(nm1, fmaxf(s[ni][2], s[ni][3]));
        }
        nm0 = fmaxf(nm0, __shfl_xor_sync(0xffffffffu, nm0, 1));
        nm0 = fmaxf(nm0, __shfl_xor_sync(0xffffffffu, nm0, 2));
        nm1 = fmaxf(nm1, __shfl_xor_sync(0xffffffffu, nm1, 1));
        nm1 = fmaxf(nm1, __shfl_xor_sync(0xffffffffu, nm1, 2));

        float corr0 = __expf(m0 - nm0);
        float corr1 = __expf(m1 - nm1);
        m0 = nm0; m1 = nm1;

        float rs0 = 0.f, rs1 = 0.f;
#pragma unroll
        for (int ni = 0; ni < 8; ni++) {
            s[ni][0] = (s[ni][0] > -1e29f) ? __expf(s[ni][0] - m0) : 0.f;
            s[ni][1] = (s[ni][1] > -1e29f) ? __expf(s[ni][1] - m0) : 0.f;
            s[ni][2] = (s[ni][2] > -1e29f) ? __expf(s[ni][2] - m1) : 0.f;
            s[ni][3] = (s[ni][3] > -1e29f) ? __expf(s[ni][3] - m1) : 0.f;
            rs0 += s[ni][0] + s[ni][1];
            rs1 += s[ni][2] + s[ni][3];
        }
        rs0 += __shfl_xor_sync(0xffffffffu, rs0, 1);
        rs0 += __shfl_xor_sync(0xffffffffu, rs0, 2);
        rs1 += __shfl_xor_sync(0xffffffffu, rs1, 1);
        rs1 += __shfl_xor_sync(0xffffffffu, rs1, 2);
        l0 = l0 * corr0 + rs0;
        l1 = l1 * corr1 + rs1;

#pragma unroll
        for (int n = 0; n < 16; n++) {
            o[n][0] *= corr0; o[n][1] *= corr0;
            o[n][2] *= corr1; o[n][3] *= corr1;
        }

        // ---- stash P (tf32) in warp-private smem rows ----
#pragma unroll
        for (int ni = 0; ni < 8; ni++) {
            *(float2*)(prow0 + ni * 8 + 2 * tig) = make_float2(f2tf(s[ni][0]), f2tf(s[ni][1]));
            *(float2*)(prow1 + ni * 8 + 2 * tig) = make_float2(f2tf(s[ni][2]), f2tf(s[ni][3]));
        }
        __syncwarp();

        // ---- O += P @ V ----
#pragma unroll
        for (int ks2 = 0; ks2 < 8; ks2++) {
            unsigned pa[4];
            pa[0] = __float_as_uint(prow0[ks2 * 8 + tig]);
            pa[1] = __float_as_uint(prow1[ks2 * 8 + tig]);
            pa[2] = __float_as_uint(prow0[ks2 * 8 + tig + 4]);
            pa[3] = __float_as_uint(prow1[ks2 * 8 + tig + 4]);
#pragma unroll
            for (int nip = 0; nip < 8; nip++) {
                uint4 vf = Vf[(ks2 * 8 + nip) * 32 + (lane ^ nip)];
                unsigned bfe[2] = {vf.x, vf.y};
                unsigned bfo[2] = {vf.z, vf.w};
                mma8(o[2 * nip],     pa, bfe);
                mma8(o[2 * nip + 1], pa, bfo);
            }
        }
    }

    // ---- normalize + store [b,s,h,d], pre-rounded to tf32 for O-proj ----
    float inv0 = (l0 > 0.f) ? (1.f / l0) : 0.f;
    float inv1 = (l1 > 0.f) ? (1.f / l1) : 0.f;
    float* ob0 = g_att + (size_t)(b * SEQ + qr0) * QINNER + h * DHEAD;
    float* ob1 = ob0 + 8 * QINNER;
#pragma unroll
    for (int ni = 0; ni < 16; ni++) {
        *(float2*)(ob0 + ni * 8 + 2 * tig) =
            make_float2(f2tf(o[ni][0] * inv0), f2tf(o[ni][1] * inv0));
        *(float2*)(ob1 + ni * 8 + 2 * tig) =
            make_float2(f2tf(o[ni][2] * inv1), f2tf(o[ni][3] * inv1));
    }
}

// ---------------------------------------------------------------------------
// Launch
// ---------------------------------------------------------------------------
extern "C" void kernel_launch(void* const* d_in, const int* in_sizes, int n_in,
                              void* d_out, int out_size)
{
    const float* x    = (const float*)d_in[0];
    const int*   mask = (const int*)  d_in[1];
    const float* Wq   = (const float*)d_in[2];
    const float* bq   = (const float*)d_in[3];
    const float* Wk   = (const float*)d_in[4];
    const float* bk   = (const float*)d_in[5];
    const float* Wv   = (const float*)d_in[6];
    const float* bv   = (const float*)d_in[7];
    const float* Wo   = (const float*)d_in[8];
    const float* bo   = (const float*)d_in[9];
    float* out = (float*)d_out;

    float *q, *k, *v, *att, *x19, *wq19, *wk19, *wv19, *wo19;
    cudaGetSymbolAddress((void**)&q,    g_q);
    cudaGetSymbolAddress((void**)&k,    g_k);
    cudaGetSymbolAddress((void**)&v,    g_v);
    cudaGetSymbolAddress((void**)&att,  g_att);
    cudaGetSymbolAddress((void**)&x19,  g_x19);
    cudaGetSymbolAddress((void**)&wq19, g_wq19);
    cudaGetSymbolAddress((void**)&wk19, g_wk19);
    cudaGetSymbolAddress((void**)&wv19, g_wv19);
    cudaGetSymbolAddress((void**)&wo19, g_wo19);

    cudaFuncSetAttribute(attn_tf32,  cudaFuncAttributeMaxDynamicSharedMemorySize, SMEM_ATTN);
    cudaFuncSetAttribute(qkv_tf32,   cudaFuncAttributeMaxDynamicSharedMemorySize, GEMM_SMEM);
    cudaFuncSetAttribute(oproj_tf32, cudaFuncAttributeMaxDynamicSharedMemorySize, GEMM_SMEM);

    dim3 thr(256);
    round_all<<<(N4_ALL + 255) / 256, thr>>>(
        (const float4*)x,  (float4*)x19,
        (const float4*)Wq, (float4*)wq19,
        (const float4*)Wk, (float4*)wk19,
        (const float4*)Wv, (float4*)wv19,
        (const float4*)Wo, (float4*)wo19);

    qkv_tf32<<<dim3(24, MROWS / TBM), thr, GEMM_SMEM>>>(x19, wq19, bq, wk19, bk, wv19, bv, q, k, v);
    kv_pack<<<(BB * NKV * SEQ * 32) / 256, thr>>>();
    attn_tf32<<<dim3(SEQ / ABQ, BB * NHEAD), dim3(ATHR), SMEM_ATTN>>>(mask);
    oproj_tf32<<<dim3(DMODEL / TBN, MROWS / TBM), thr, GEMM_SMEM>>>(att, wo19, bo, out);
}

// round 12
// speedup vs baseline: 1.3381x; 1.2181x over previous
#include <cuda_runtime.h>
#include <cuda_fp16.h>
#include <math.h>

// ---------------------------------------------------------------------------
// Problem constants
// ---------------------------------------------------------------------------
#define BB      2
#define SEQ     2048
#define DMODEL  2048
#define NHEAD   16
#define NKV     4
#define DHEAD   128
#define QINNER  (NHEAD * DHEAD)    // 2048
#define KVINNER (NKV * DHEAD)      // 512
#define NREP    (NHEAD / NKV)      // 4
#define MROWS   (BB * SEQ)         // 4096
#define NTILE   (SEQ / 64)         // 32 KV tiles per (b,kh)

// Scratch (allocation-free rule: device globals)
__device__ __half g_qh[MROWS * QINNER];    // fp16 q (qkv epilogue)
__device__ __half g_kh[MROWS * KVINNER];   // fp16 k
__device__ __half g_vh[MROWS * KVINNER];   // fp16 v
__device__ float  g_att[MROWS * QINNER];   // tf32-rounded attention output
// K/V in fp16 m16n8k16 fragment-major layout: [b][kh][tile] x 8192 halves
__device__ __half g_kf16[BB * NKV * NTILE * 8192];
__device__ __half g_vf16[BB * NKV * NTILE * 8192];
// tf32-pre-rounded copies of GEMM inputs (HW truncation becomes exact RNA)
__device__ float g_x19[MROWS * DMODEL];
__device__ float g_wq19[QINNER * DMODEL];
__device__ float g_wk19[KVINNER * DMODEL];
__device__ float g_wv19[KVINNER * DMODEL];
__device__ float g_wo19[DMODEL * QINNER];

// ---------------------------------------------------------------------------
// helpers
// ---------------------------------------------------------------------------
__device__ __forceinline__ float f2tf(float x) {
    unsigned y;
    asm("cvt.rna.tf32.f32 %0, %1;" : "=r"(y) : "f"(x));
    return __uint_as_float(y);
}

// tf32: D(16x8) += A(16x8) * B(8x8)
__device__ __forceinline__ void mma8(float* d, const unsigned* a, const unsigned* b) {
    asm("mma.sync.aligned.m16n8k8.row.col.f32.tf32.tf32.f32 "
        "{%0,%1,%2,%3},{%4,%5,%6,%7},{%8,%9},{%0,%1,%2,%3};"
        : "+f"(d[0]), "+f"(d[1]), "+f"(d[2]), "+f"(d[3])
        : "r"(a[0]), "r"(a[1]), "r"(a[2]), "r"(a[3]), "r"(b[0]), "r"(b[1]));
}

// fp16: D(16x8,f32) += A(16x16,f16) * B(16x8,f16)
__device__ __forceinline__ void mma16(float* d, const unsigned* a, unsigned b0, unsigned b1) {
    asm("mma.sync.aligned.m16n8k16.row.col.f32.f16.f16.f32 "
        "{%0,%1,%2,%3},{%4,%5,%6,%7},{%8,%9},{%0,%1,%2,%3};"
        : "+f"(d[0]), "+f"(d[1]), "+f"(d[2]), "+f"(d[3])
        : "r"(a[0]), "r"(a[1]), "r"(a[2]), "r"(a[3]), "r"(b0), "r"(b1));
}

__device__ __forceinline__ void cp16(unsigned s, const void* g) {
    asm volatile("cp.async.cg.shared.global [%0], [%1], 16;\n" :: "r"(s), "l"(g));
}

// ---------------------------------------------------------------------------
// Fused RNA round-to-tf32 of all five GEMM inputs (one launch)
// ---------------------------------------------------------------------------
#define N4_X   (MROWS * DMODEL / 4)
#define N4_WQ  (QINNER * DMODEL / 4)
#define N4_WKV (KVINNER * DMODEL / 4)
#define N4_WO  (DMODEL * QINNER / 4)
#define N4_ALL (N4_X + N4_WQ + 2 * N4_WKV + N4_WO)

__global__ __launch_bounds__(256)
void round_all(const float4* __restrict__ x,  float4* __restrict__ xo,
               const float4* __restrict__ wq, float4* __restrict__ wqo,
               const float4* __restrict__ wk, float4* __restrict__ wko,
               const float4* __restrict__ wv, float4* __restrict__ wvo,
               const float4* __restrict__ wo, float4* __restrict__ woo)
{
    int i = blockIdx.x * blockDim.x + threadIdx.x;
    if (i >= N4_ALL) return;
    const float4* src; float4* dst; int off;
    if (i < N4_X)                            { src = x;  dst = xo;  off = i; }
    else if (i < N4_X + N4_WQ)               { src = wq; dst = wqo; off = i - N4_X; }
    else if (i < N4_X + N4_WQ + N4_WKV)      { src = wk; dst = wko; off = i - N4_X - N4_WQ; }
    else if (i < N4_X + N4_WQ + 2 * N4_WKV)  { src = wv; dst = wvo; off = i - N4_X - N4_WQ - N4_WKV; }
    else                                     { src = wo; dst = woo; off = i - N4_X - N4_WQ - 2 * N4_WKV; }
    float4 v = src[off];
    v.x = f2tf(v.x); v.y = f2tf(v.y); v.z = f2tf(v.z); v.w = f2tf(v.w);
    dst[off] = v;
}

// ---------------------------------------------------------------------------
// kv_pack: permute fp16 K/V into m16n8k16 fragment-major tiles (pure bits).
// thread = (b, kh, s, lane); lane covers 4 consecutive d.
// K b-frag (S mma): src (r=key,d): ks=d>>4, dd=d&15, breg=dd>=8, tig=(dd&7)>>1,
//   hp=dd&1, ni=r>>3, gK=r&7 -> half idx ((ks*4+(ni>>1))*32+gK*4+tig)*8 + ((ni&1)*2+breg)*2 + hp
// V b-frag (PV mma): src (r=key,d): ks2=r>>4, kk=r&15, breg=kk>=8, tigv=(kk&7)>>1,
//   hp=kk&1, ni=d>>3, gV=d&7 -> ((ks2*8+(ni>>1))*32+gV*4+tigv)*8 + ((ni&1)*2+breg)*2 + hp
// ---------------------------------------------------------------------------
__global__ __launch_bounds__(256)
void kv_pack()
{
    int gidx  = blockIdx.x * 256 + threadIdx.x;     // 0 .. 524287
    int lane  = gidx & 31;                          // d-group (d = lane*4)
    int s_lin = gidx >> 5;
    int s  = s_lin & (SEQ - 1);
    int bk = s_lin >> 11;
    int b  = bk >> 2;
    int kh = bk & 3;

    size_t goff = (size_t)(b * SEQ + s) * KVINNER + kh * DHEAD + lane * 4;
    union { uint2 u; unsigned short h[4]; } ku, vu;
    ku.u = *(const uint2*)(g_kh + goff);
    vu.u = *(const uint2*)(g_vh + goff);

    int r = s & 63;
    int t = s >> 6;
    size_t tb = ((size_t)(b * NKV + kh) * NTILE + t) << 13;   // *8192 halves
    unsigned short* kdst = (unsigned short*)g_kf16 + tb;
    unsigned short* vdst = (unsigned short*)g_vf16 + tb;

    int d0 = lane * 4;
    // ---- K: 4 halves -> two half2 stores ----
    {
        int ks = d0 >> 4, dd0 = d0 & 15;
        int breg = (dd0 >> 3) & 1;
        int ni = r >> 3, gK = r & 7;
        int w2 = (((ni & 1) << 1) | breg) << 1;          // w*2
        int u4 = ((ks * 4 + (ni >> 1)) * 32 + gK * 4) * 8;
        int tigA = (dd0 & 7) >> 1;
        unsigned p0 = (unsigned)ku.h[0] | ((unsigned)ku.h[1] << 16);
        unsigned p1 = (unsigned)ku.h[2] | ((unsigned)ku.h[3] << 16);
        *(unsigned*)(kdst + u4 + tigA * 8 + w2)       = p0;
        *(unsigned*)(kdst + u4 + (tigA + 1) * 8 + w2) = p1;
    }
    // ---- V: 4 scalar half stores (transpose-style scatter) ----
    {
        int ks2 = r >> 4, kk = r & 15;
        int breg = (kk >> 3) & 1;
        int tigv = (kk & 7) >> 1;
        int hp = kk & 1;
        int ni = d0 >> 3;
        int w2hp = ((((ni & 1) << 1) | breg) << 1) + hp;
        int base = (ks2 * 8 + (ni >> 1)) * 32 * 8 + tigv * 8 + w2hp;
#pragma unroll
        for (int j = 0; j < 4; j++) {
            int gV = (d0 & 7) + j;
            vdst[base + gV * 32] = vu.h[j];
        }
    }
}

// ---------------------------------------------------------------------------
// tf32 GEMM body: C = A @ W^T + bias. Padded smem + cp.async 2-stage pipeline.
// HALF_OUT: emit fp16 (for q/k/v feeding fp16 attention).
// ---------------------------------------------------------------------------
#define TBM 128
#define TBN 128
#define TBK 32
#define TPAD 36
#define GEMM_SMEM (2 * 2 * TBM * TPAD * 4)   // 73728 bytes

template<bool HALF_OUT>
__device__ __forceinline__
void gemm_body(const float* __restrict__ A, const float* __restrict__ W,
               const float* __restrict__ bias, void* __restrict__ C,
               int N, int K, int bm, int bn, float* As, float* Ws)
{
    const int tid   = threadIdx.x;
    const int lane  = tid & 31;
    const int wid   = tid >> 5;
    const int gID   = lane >> 2;
    const int tig   = lane & 3;
    const int wmSel = wid & 1;
    const int wnSel = wid >> 1;
    const unsigned asb = (unsigned)__cvta_generic_to_shared(As);
    const unsigned wsb = (unsigned)__cvta_generic_to_shared(Ws);

    float acc[4][4][4];
#pragma unroll
    for (int mi = 0; mi < 4; mi++)
#pragma unroll
        for (int ni = 0; ni < 4; ni++)
#pragma unroll
            for (int j = 0; j < 4; j++) acc[mi][ni][j] = 0.f;

    const int NT = K / TBK;

#pragma unroll
    for (int it = 0; it < 4; it++) {
        int idx = tid + it * 256, row = idx >> 3, c4 = (idx & 7) << 2;
        cp16(asb + (unsigned)((row * TPAD + c4) << 2), A + (size_t)(bm + row) * K + c4);
        cp16(wsb + (unsigned)((row * TPAD + c4) << 2), W + (size_t)(bn + row) * K + c4);
    }
    asm volatile("cp.async.commit_group;\n");

    for (int kt = 0; kt < NT; kt++) {
        int buf = kt & 1;
        if (kt + 1 < NT) {
            int k0n = (kt + 1) * TBK, bufn = (kt + 1) & 1;
#pragma unroll
            for (int it = 0; it < 4; it++) {
                int idx = tid + it * 256, row = idx >> 3, c4 = (idx & 7) << 2;
                cp16(asb + (unsigned)(((bufn * TBM + row) * TPAD + c4) << 2),
                     A + (size_t)(bm + row) * K + k0n + c4);
                cp16(wsb + (unsigned)(((bufn * TBM + row) * TPAD + c4) << 2),
                     W + (size_t)(bn + row) * K + k0n + c4);
            }
            asm volatile("cp.async.commit_group;\n");
            asm volatile("cp.async.wait_group 1;\n");
        } else {
            asm volatile("cp.async.wait_group 0;\n");
        }
        __syncthreads();

        const float* Ab = As + buf * TBM * TPAD;
        const float* Wb = Ws + buf * TBM * TPAD;
#pragma unroll
        for (int ks = 0; ks < 4; ks++) {
            unsigned af[4][4], bf[4][2];
#pragma unroll
            for (int mi = 0; mi < 4; mi++) {
                int r = wmSel * 64 + mi * 16 + gID;
                af[mi][0] = __float_as_uint(Ab[r * TPAD + ks * 8 + tig]);
                af[mi][1] = __float_as_uint(Ab[(r + 8) * TPAD + ks * 8 + tig]);
                af[mi][2] = __float_as_uint(Ab[r * TPAD + ks * 8 + tig + 4]);
                af[mi][3] = __float_as_uint(Ab[(r + 8) * TPAD + ks * 8 + tig + 4]);
            }
#pragma unroll
            for (int ni = 0; ni < 4; ni++) {
                int c = wnSel * 32 + ni * 8 + gID;
                bf[ni][0] = __float_as_uint(Wb[c * TPAD + ks * 8 + tig]);
                bf[ni][1] = __float_as_uint(Wb[c * TPAD + ks * 8 + tig + 4]);
            }
#pragma unroll
            for (int mi = 0; mi < 4; mi++)
#pragma unroll
                for (int ni = 0; ni < 4; ni++)
                    mma8(acc[mi][ni], af[mi], bf[ni]);
        }
        __syncthreads();
    }

    const int wm = wmSel * 64;
    const int wn = wnSel * 32;
#pragma unroll
    for (int mi = 0; mi < 4; mi++) {
        int r = bm + wm + mi * 16 + gID;
#pragma unroll
        for (int ni = 0; ni < 4; ni++) {
            int c = bn + wn + ni * 8 + 2 * tig;
            float2 bv = *(const float2*)(bias + c);
            float o0 = acc[mi][ni][0] + bv.x, o1 = acc[mi][ni][1] + bv.y;
            float o2 = acc[mi][ni][2] + bv.x, o3 = acc[mi][ni][3] + bv.y;
            if (HALF_OUT) {
                __half* Ch = (__half*)C;
                *(__half2*)(Ch + (size_t)r * N + c)       = __floats2half2_rn(o0, o1);
                *(__half2*)(Ch + (size_t)(r + 8) * N + c) = __floats2half2_rn(o2, o3);
            } else {
                float* Cf = (float*)C;
                *(float2*)(Cf + (size_t)r * N + c)       = make_float2(o0, o1);
                *(float2*)(Cf + (size_t)(r + 8) * N + c) = make_float2(o2, o3);
            }
        }
    }
}

__global__ __launch_bounds__(256, 2)
void qkv_tf32(const float* __restrict__ x,
              const float* __restrict__ Wq, const float* __restrict__ bq,
              const float* __restrict__ Wk, const float* __restrict__ bk,
              const float* __restrict__ Wv, const float* __restrict__ bv)
{
    extern __shared__ float dsm[];
    float* As = dsm;
    float* Ws = dsm + 2 * TBM * TPAD;
    int bx = blockIdx.x;
    const float *W, *bias; __half* C; int N, bn;
    if (bx < 16)      { W = Wq; bias = bq; C = g_qh; N = QINNER;  bn = bx * 128; }
    else if (bx < 20) { W = Wk; bias = bk; C = g_kh; N = KVINNER; bn = (bx - 16) * 128; }
    else              { W = Wv; bias = bv; C = g_vh; N = KVINNER; bn = (bx - 20) * 128; }
    gemm_body<true>(x, W, bias, C, N, DMODEL, blockIdx.y * TBM, bn, As, Ws);
}

__global__ __launch_bounds__(256, 2)
void oproj_tf32(const float* __restrict__ A, const float* __restrict__ Wo,
                const float* __restrict__ bo, float* __restrict__ C)
{
    extern __shared__ float dsm[];
    float* As = dsm;
    float* Ws = dsm + 2 * TBM * TPAD;
    gemm_body<false>(A, Wo, bo, C, DMODEL, QINNER, blockIdx.y * TBM, blockIdx.x * TBN, As, Ws);
}

// ---------------------------------------------------------------------------
// fp16 flash attention (m16n8k16, fp32 accum). K/V pre-packed fragment-major;
// double-buffered cp.async tiles. ABQ=64, 4 warps, 2 CTAs/SM.
// ---------------------------------------------------------------------------
#define ABQ   64
#define ABK   64
#define ATHR  128
#define PPADH 72
#define TILE_H 8192                 // halves per K (or V) tile = 16KB
#define SMEM_ATTN (4 * 16384 + ABQ * PPADH * 2)   // 2xKbuf + 2xVbuf + Ps = 74752

__global__ __launch_bounds__(ATHR, 2)
void attn_fp16(const int* __restrict__ mask)
{
    extern __shared__ char smc[];
    const unsigned kfs = (unsigned)__cvta_generic_to_shared(smc);           // K bufs at 0, 16K
    const unsigned vfs = kfs + 32768;                                       // V bufs at 32K, 48K
    __half* Ps = (__half*)(smc + 65536);                                    // [64][PPADH]

    const int tid  = threadIdx.x;
    const int lane = tid & 31;
    const int wid  = tid >> 5;
    const int gID  = lane >> 2;
    const int tig  = lane & 3;
    const int q0   = blockIdx.x * ABQ;
    const int bh   = blockIdx.y;
    const int b    = bh >> 4;
    const int h    = bh & 15;
    const int kh   = h >> 2;
    const float scale = 0.08838834764831845f;   // 1/sqrt(128)

    const __half* kblk0 = g_kf16 + ((size_t)(b * NKV + kh) * NTILE) * TILE_H;
    const __half* vblk0 = g_vf16 + ((size_t)(b * NKV + kh) * NTILE) * TILE_H;

    // ---- Q a-frags in registers (fp16, 8 k-steps of 16) ----
    const int qr0 = q0 + wid * 16 + gID;
    const unsigned* qb0 = (const unsigned*)(g_qh + (size_t)(b * SEQ + qr0) * QINNER + h * DHEAD);
    const unsigned* qb1 = qb0 + 8 * QINNER / 2;
    unsigned qa[8][4];
#pragma unroll
    for (int ks = 0; ks < 8; ks++) {
        qa[ks][0] = qb0[8 * ks + tig];
        qa[ks][1] = qb1[8 * ks + tig];
        qa[ks][2] = qb0[8 * ks + tig + 4];
        qa[ks][3] = qb1[8 * ks + tig + 4];
    }

    float o[16][4];
#pragma unroll
    for (int n = 0; n < 16; n++)
#pragma unroll
        for (int j = 0; j < 4; j++) o[n][j] = 0.f;
    float m0 = -1e30f, m1 = -1e30f, l0 = 0.f, l1 = 0.f;

    const int* mrow0 = mask + (size_t)b * SEQ * SEQ + (size_t)qr0 * SEQ;
    const int* mrow1 = mrow0 + 8 * SEQ;

    __half* prow0 = Ps + (wid * 16 + gID) * PPADH;
    __half* prow1 = prow0 + 8 * PPADH;

    // prefetch tile 0 into buffer 0
#pragma unroll
    for (int it = 0; it < 8; it++) {
        int u = tid + it * ATHR;
        cp16(kfs + u * 16, kblk0 + u * 8);
        cp16(vfs + u * 16, vblk0 + u * 8);
    }
    asm volatile("cp.async.commit_group;\n");

    for (int t = 0; t < NTILE; t++) {
        int buf = t & 1;
        if (t + 1 < NTILE) {
            int bn = buf ^ 1;
            const __half* kb = kblk0 + (size_t)(t + 1) * TILE_H;
            const __half* vb = vblk0 + (size_t)(t + 1) * TILE_H;
#pragma unroll
            for (int it = 0; it < 8; it++) {
                int u = tid + it * ATHR;
                cp16(kfs + bn * 16384 + u * 16, kb + u * 8);
                cp16(vfs + bn * 16384 + u * 16, vb + u * 8);
            }
            asm volatile("cp.async.commit_group;\n");
            asm volatile("cp.async.wait_group 1;\n");
        } else {
            asm volatile("cp.async.wait_group 0;\n");
        }
        __syncthreads();

        const uint4* Kf = (const uint4*)(smc + buf * 16384);
        const uint4* Vf = (const uint4*)(smc + 32768 + buf * 16384);
        const int k0 = t * ABK;

        // ---- S = Q @ K^T  (8 d-chunks of 16, 8 key-tiles of 8) ----
        float s[8][4];
#pragma unroll
        for (int ni = 0; ni < 8; ni++)
#pragma unroll
            for (int j = 0; j < 4; j++) s[ni][j] = 0.f;

#pragma unroll
        for (int ks = 0; ks < 8; ks++) {
#pragma unroll
            for (int nip = 0; nip < 4; nip++) {
                uint4 kf = Kf[(ks * 4 + nip) * 32 + lane];
                mma16(s[2 * nip],     qa[ks], kf.x, kf.y);
                mma16(s[2 * nip + 1], qa[ks], kf.z, kf.w);
            }
        }

        // ---- scale + mask + online softmax ----
        float nm0 = m0, nm1 = m1;
#pragma unroll
        for (int ni = 0; ni < 8; ni++) {
            int cc = k0 + ni * 8 + 2 * tig;
            int2 mm0 = *(const int2*)(mrow0 + cc);
            int2 mm1 = *(const int2*)(mrow1 + cc);
            s[ni][0] = mm0.x ? s[ni][0] * scale : -1e30f;
            s[ni][1] = mm0.y ? s[ni][1] * scale : -1e30f;
            s[ni][2] = mm1.x ? s[ni][2] * scale : -1e30f;
            s[ni][3] = mm1.y ? s[ni][3] * scale : -1e30f;
            nm0 = fmaxf(nm0, fmaxf(s[ni][0], s[ni][1]));
            nm1 = fmaxf(nm1, fmaxf(s[ni][2], s[ni][3]));
        }
        nm0 = fmaxf(nm0, __shfl_xor_sync(0xffffffffu, nm0, 1));
        nm0 = fmaxf(nm0, __shfl_xor_sync(0xffffffffu, nm0, 2));
        nm1 = fmaxf(nm1, __shfl_xor_sync(0xffffffffu, nm1, 1));
        nm1 = fmaxf(nm1, __shfl_xor_sync(0xffffffffu, nm1, 2));

        float corr0 = __expf(m0 - nm0);
        float corr1 = __expf(m1 - nm1);
        m0 = nm0; m1 = nm1;

        float rs0 = 0.f, rs1 = 0.f;
#pragma unroll
        for (int ni = 0; ni < 8; ni++) {
            s[ni][0] = (s[ni][0] > -1e29f) ? __expf(s[ni][0] - m0) : 0.f;
            s[ni][1] = (s[ni][1] > -1e29f) ? __expf(s[ni][1] - m0) : 0.f;
            s[ni][2] = (s[ni][2] > -1e29f) ? __expf(s[ni][2] - m1) : 0.f;
            s[ni][3] = (s[ni][3] > -1e29f) ? __expf(s[ni][3] - m1) : 0.f;
            rs0 += s[ni][0] + s[ni][1];
            rs1 += s[ni][2] + s[ni][3];
        }
        rs0 += __shfl_xor_sync(0xffffffffu, rs0, 1);
        rs0 += __shfl_xor_sync(0xffffffffu, rs0, 2);
        rs1 += __shfl_xor_sync(0xffffffffu, rs1, 1);
        rs1 += __shfl_xor_sync(0xffffffffu, rs1, 2);
        l0 = l0 * corr0 + rs0;
        l1 = l1 * corr1 + rs1;

#pragma unroll
        for (int n = 0; n < 16; n++) {
            o[n][0] *= corr0; o[n][1] *= corr0;
            o[n][2] *= corr1; o[n][3] *= corr1;
        }

        // ---- stash P (fp16) in warp-private smem rows ----
#pragma unroll
        for (int ni = 0; ni < 8; ni++) {
            *(__half2*)(prow0 + ni * 8 + 2 * tig) = __floats2half2_rn(s[ni][0], s[ni][1]);
            *(__half2*)(prow1 + ni * 8 + 2 * tig) = __floats2half2_rn(s[ni][2], s[ni][3]);
        }
        __syncwarp();

        // ---- O += P @ V  (4 key-chunks of 16, 16 d-tiles of 8) ----
#pragma unroll
        for (int ks2 = 0; ks2 < 4; ks2++) {
            unsigned pa[4];
            pa[0] = *(const unsigned*)(prow0 + 16 * ks2 + 2 * tig);
            pa[1] = *(const unsigned*)(prow1 + 16 * ks2 + 2 * tig);
            pa[2] = *(const unsigned*)(prow0 + 16 * ks2 + 2 * tig + 8);
            pa[3] = *(const unsigned*)(prow1 + 16 * ks2 + 2 * tig + 8);
#pragma unroll
            for (int nip = 0; nip < 8; nip++) {
                uint4 vf = Vf[(ks2 * 8 + nip) * 32 + lane];
                mma16(o[2 * nip],     pa, vf.x, vf.y);
                mma16(o[2 * nip + 1], pa, vf.z, vf.w);
            }
        }
        __syncthreads();
    }

    // ---- normalize + store [b,s,h,d], pre-rounded to tf32 for O-proj ----
    float inv0 = (l0 > 0.f) ? (1.f / l0) : 0.f;
    float inv1 = (l1 > 0.f) ? (1.f / l1) : 0.f;
    float* ob0 = g_att + (size_t)(b * SEQ + qr0) * QINNER + h * DHEAD;
    float* ob1 = ob0 + 8 * QINNER;
#pragma unroll
    for (int ni = 0; ni < 16; ni++) {
        *(float2*)(ob0 + ni * 8 + 2 * tig) =
            make_float2(f2tf(o[ni][0] * inv0), f2tf(o[ni][1] * inv0));
        *(float2*)(ob1 + ni * 8 + 2 * tig) =
            make_float2(f2tf(o[ni][2] * inv1), f2tf(o[ni][3] * inv1));
    }
}

// ---------------------------------------------------------------------------
// Launch
// ---------------------------------------------------------------------------
extern "C" void kernel_launch(void* const* d_in, const int* in_sizes, int n_in,
                              void* d_out, int out_size)
{
    const float* x    = (const float*)d_in[0];
    const int*   mask = (const int*)  d_in[1];
    const float* Wq   = (const float*)d_in[2];
    const float* bq   = (const float*)d_in[3];
    const float* Wk   = (const float*)d_in[4];
    const float* bk   = (const float*)d_in[5];
    const float* Wv   = (const float*)d_in[6];
    const float* bv   = (const float*)d_in[7];
    const float* Wo   = (const float*)d_in[8];
    const float* bo   = (const float*)d_in[9];
    float* out = (float*)d_out;

    float *att, *x19, *wq19, *wk19, *wv19, *wo19;
    cudaGetSymbolAddress((void**)&att,  g_att);
    cudaGetSymbolAddress((void**)&x19,  g_x19);
    cudaGetSymbolAddress((void**)&wq19, g_wq19);
    cudaGetSymbolAddress((void**)&wk19, g_wk19);
    cudaGetSymbolAddress((void**)&wv19, g_wv19);
    cudaGetSymbolAddress((void**)&wo19, g_wo19);

    cudaFuncSetAttribute(attn_fp16,  cudaFuncAttributeMaxDynamicSharedMemorySize, SMEM_ATTN);
    cudaFuncSetAttribute(qkv_tf32,   cudaFuncAttributeMaxDynamicSharedMemorySize, GEMM_SMEM);
    cudaFuncSetAttribute(oproj_tf32, cudaFuncAttributeMaxDynamicSharedMemorySize, GEMM_SMEM);

    dim3 thr(256);
    round_all<<<(N4_ALL + 255) / 256, thr>>>(
        (const float4*)x,  (float4*)x19,
        (const float4*)Wq, (float4*)wq19,
        (const float4*)Wk, (float4*)wk19,
        (const float4*)Wv, (float4*)wv19,
        (const float4*)Wo, (float4*)wo19);

    qkv_tf32<<<dim3(24, MROWS / TBM), thr, GEMM_SMEM>>>(x19, wq19, bq, wk19, bk, wv19, bv);
    kv_pack<<<(BB * NKV * SEQ * 32) / 256, thr>>>();
    attn_fp16<<<dim3(SEQ / ABQ, BB * NHEAD), dim3(ATHR), SMEM_ATTN>>>(mask);
    oproj_tf32<<<dim3(DMODEL / TBN, MROWS / TBM), thr, GEMM_SMEM>>>(att, wo19, bo, out);
}

// round 14
// speedup vs baseline: 2.1410x; 1.6000x over previous
#include <cuda_runtime.h>
#include <cuda_fp16.h>
#include <math.h>

// ---------------------------------------------------------------------------
// Problem constants
// ---------------------------------------------------------------------------
#define BB      2
#define SEQ     2048
#define DMODEL  2048
#define NHEAD   16
#define NKV     4
#define DHEAD   128
#define QINNER  (NHEAD * DHEAD)    // 2048
#define KVINNER (NKV * DHEAD)      // 512
#define NREP    (NHEAD / NKV)      // 4
#define MROWS   (BB * SEQ)         // 4096
#define NTILE   (SEQ / 64)         // 32 KV tiles per (b,kh)
#define NKT     (DMODEL / 32)      // 64 k-tiles (K=2048 for all GEMMs)
#define HBLK    4096               // halves per 128x32 fragment block (8KB)

// Scratch (allocation-free rule: device globals)
__device__ __half g_qh[MROWS * QINNER];    // fp16 q, linear (qkv epilogue)
__device__ __half g_kh[MROWS * KVINNER];   // fp16 k, linear
__device__ __half g_vh[MROWS * KVINNER];   // fp16 v, linear
// fragment-major fp16 operands for GEMMs (blocks of 128x32 = 4096 halves)
__device__ __half g_xf [32 * NKT * HBLK];  // X  [rt=32][kt=64]
__device__ __half g_wqf[16 * NKT * HBLK];  // Wq [nt=16][kt]
__device__ __half g_wkf[ 4 * NKT * HBLK];  // Wk [nt=4]
__device__ __half g_wvf[ 4 * NKT * HBLK];  // Wv
__device__ __half g_wof[16 * NKT * HBLK];  // Wo [nt=16]
__device__ __half g_attf[32 * NKT * HBLK]; // att [rt=32][kt] (attn epilogue)
// K/V in fp16 m16n8k16 fragment-major attention tiles
__device__ __half g_kf16[BB * NKV * NTILE * 8192];
__device__ __half g_vf16[BB * NKV * NTILE * 8192];

// bias pointers for the fused qkv kernel
__device__ const float* g_bq;
__device__ const float* g_bk;
__device__ const float* g_bv;

// ---------------------------------------------------------------------------
// helpers
// ---------------------------------------------------------------------------
// fp16: D(16x8,f32) += A(16x16,f16) * B(16x8,f16)
__device__ __forceinline__ void mma16(float* d, const unsigned* a, unsigned b0, unsigned b1) {
    asm("mma.sync.aligned.m16n8k16.row.col.f32.f16.f16.f32 "
        "{%0,%1,%2,%3},{%4,%5,%6,%7},{%8,%9},{%0,%1,%2,%3};"
        : "+f"(d[0]), "+f"(d[1]), "+f"(d[2]), "+f"(d[3])
        : "r"(a[0]), "r"(a[1]), "r"(a[2]), "r"(a[3]), "r"(b0), "r"(b1));
}

__device__ __forceinline__ void cp16(unsigned s, const void* g) {
    asm volatile("cp.async.cg.shared.global [%0], [%1], 16;\n" :: "r"(s), "l"(g));
}

__device__ __forceinline__ unsigned pack2h(float a, float b) {
    __half2 h = __floats2half2_rn(a, b);
    return *(unsigned*)&h;
}

// ---------------------------------------------------------------------------
// pack_all: convert fp32 inputs to fp16 and permute into fragment-major
// 128x32 blocks.  A-layout (m-major operand), B-layout (n-major operand).
// Each thread handles 4 consecutive k of one row.
// ---------------------------------------------------------------------------
__device__ __forceinline__
void pack_a4(unsigned short* dst, float4 v, int r, int k0)
{
    unsigned p0 = pack2h(v.x, v.y), p1 = pack2h(v.z, v.w);
    int rt = r >> 7, rr = r & 127, kt = k0 >> 5, kk = k0 & 31;
    int ks = kk >> 4, kkk = kk & 15;
    int mi = rr >> 4, gID = rr & 7, hsel = (rr >> 3) & 1;
    int tigA = (kkk & 7) >> 1, breg = kkk >> 3;
    int areg = (breg << 1) | hsel;
    unsigned short* b = dst + (size_t)(rt * NKT + kt) * HBLK
                      + ((ks * 8 + mi) * 32 + gID * 4) * 8 + areg * 2;
    *(unsigned*)(b + tigA * 8)       = p0;
    *(unsigned*)(b + (tigA + 1) * 8) = p1;
}

__device__ __forceinline__
void pack_b4(unsigned short* dst, float4 v, int c, int k0)
{
    unsigned p0 = pack2h(v.x, v.y), p1 = pack2h(v.z, v.w);
    int nt = c >> 7, cc = c & 127, kt = k0 >> 5, kk = k0 & 31;
    int ks = kk >> 4, kkk = kk & 15;
    int nj = cc >> 3, gID = cc & 7;
    int u = ks * 8 + (nj >> 1);
    int w = ((nj & 1) << 1) | (kkk >> 3);
    int tig = (kkk & 7) >> 1;
    unsigned short* b = dst + (size_t)(nt * NKT + kt) * HBLK
                      + (u * 32 + gID * 4) * 8 + w * 2;
    *(unsigned*)(b + tig * 8)       = p0;
    *(unsigned*)(b + (tig + 1) * 8) = p1;
}

#define GX   (MROWS * 512)      // 2097152 groups (K=2048/4)
#define GWQ  (QINNER * 512)
#define GWKV (KVINNER * 512)
#define GWO  (DMODEL * 512)
#define GALL (GX + GWQ + 2 * GWKV + GWO)

__global__ __launch_bounds__(256)
void pack_all(const float4* __restrict__ x,  const float4* __restrict__ wq,
              const float4* __restrict__ wk, const float4* __restrict__ wv,
              const float4* __restrict__ wo)
{
    int i = blockIdx.x * 256 + threadIdx.x;
    if (i >= GALL) return;
    if (i < GX) {
        int r = i >> 9, kg = i & 511;
        pack_a4((unsigned short*)g_xf, x[(size_t)r * 512 + kg], r, kg * 4);
    } else if (i < GX + GWQ) {
        int j = i - GX; int c = j >> 9, kg = j & 511;
        pack_b4((unsigned short*)g_wqf, wq[(size_t)c * 512 + kg], c, kg * 4);
    } else if (i < GX + GWQ + GWKV) {
        int j = i - GX - GWQ; int c = j >> 9, kg = j & 511;
        pack_b4((unsigned short*)g_wkf, wk[(size_t)c * 512 + kg], c, kg * 4);
    } else if (i < GX + GWQ + 2 * GWKV) {
        int j = i - GX - GWQ - GWKV; int c = j >> 9, kg = j & 511;
        pack_b4((unsigned short*)g_wvf, wv[(size_t)c * 512 + kg], c, kg * 4);
    } else {
        int j = i - GX - GWQ - 2 * GWKV; int c = j >> 9, kg = j & 511;
        pack_b4((unsigned short*)g_wof, wo[(size_t)c * 512 + kg], c, kg * 4);
    }
}

// ---------------------------------------------------------------------------
// kv_pack: permute fp16 K/V into m16n8k16 attention fragment tiles (pure bits).
// ---------------------------------------------------------------------------
__global__ __launch_bounds__(256)
void kv_pack()
{
    int gidx  = blockIdx.x * 256 + threadIdx.x;
    int lane  = gidx & 31;
    int s_lin = gidx >> 5;
    int s  = s_lin & (SEQ - 1);
    int bk = s_lin >> 11;
    int b  = bk >> 2;
    int kh = bk & 3;

    size_t goff = (size_t)(b * SEQ + s) * KVINNER + kh * DHEAD + lane * 4;
    union { uint2 u; unsigned short h[4]; } ku, vu;
    ku.u = *(const uint2*)(g_kh + goff);
    vu.u = *(const uint2*)(g_vh + goff);

    int r = s & 63;
    int t = s >> 6;
    size_t tb = ((size_t)(b * NKV + kh) * NTILE + t) << 13;
    unsigned short* kdst = (unsigned short*)g_kf16 + tb;
    unsigned short* vdst = (unsigned short*)g_vf16 + tb;

    int d0 = lane * 4;
    {
        int ks = d0 >> 4, dd0 = d0 & 15;
        int breg = (dd0 >> 3) & 1;
        int ni = r >> 3, gK = r & 7;
        int w2 = (((ni & 1) << 1) | breg) << 1;
        int u4 = ((ks * 4 + (ni >> 1)) * 32 + gK * 4) * 8;
        int tigA = (dd0 & 7) >> 1;
        unsigned p0 = (unsigned)ku.h[0] | ((unsigned)ku.h[1] << 16);
        unsigned p1 = (unsigned)ku.h[2] | ((unsigned)ku.h[3] << 16);
        *(unsigned*)(kdst + u4 + tigA * 8 + w2)       = p0;
        *(unsigned*)(kdst + u4 + (tigA + 1) * 8 + w2) = p1;
    }
    {
        int ks2 = r >> 4, kk = r & 15;
        int breg = (kk >> 3) & 1;
        int tigv = (kk & 7) >> 1;
        int hp = kk & 1;
        int ni = d0 >> 3;
        int w2hp = ((((ni & 1) << 1) | breg) << 1) + hp;
        int base = (ks2 * 8 + (ni >> 1)) * 32 * 8 + tigv * 8 + w2hp;
#pragma unroll
        for (int j = 0; j < 4; j++) {
            int gV = (d0 & 7) + j;
            vdst[base + gV * 32] = vu.h[j];
        }
    }
}

// ---------------------------------------------------------------------------
// fp16 GEMM: C = A @ W^T + bias, operands pre-packed fragment-major.
// 128x128x32 tiles, 8 warps (2 wm x 4 wn), warp 64x32 via m16n8k16.
// Double-buffered contiguous cp.async fills.
// ---------------------------------------------------------------------------
#define GEMM16_SMEM (4 * 8192)   // 2 bufs x (8KB A + 8KB B) = 32768

template<bool HALF_OUT>
__device__ __forceinline__
void gemm16_body(const __half* __restrict__ Ag, const __half* __restrict__ Bg,
                 const float* __restrict__ bias, void* __restrict__ C,
                 int N, int bm, int bn, char* smc)
{
    const int tid   = threadIdx.x;
    const int lane  = tid & 31;
    const int wid   = tid >> 5;
    const int gID   = lane >> 2;
    const int tig   = lane & 3;
    const int wmSel = wid & 1;
    const int wnSel = wid >> 1;
    const unsigned sb = (unsigned)__cvta_generic_to_shared(smc);

    float acc[4][4][4];
#pragma unroll
    for (int mi = 0; mi < 4; mi++)
#pragma unroll
        for (int ni = 0; ni < 4; ni++)
#pragma unroll
            for (int j = 0; j < 4; j++) acc[mi][ni][j] = 0.f;

    // prefetch kt 0 into buf 0
#pragma unroll
    for (int it = 0; it < 2; it++) {
        int u = tid + it * 256;
        cp16(sb + u * 16, Ag + u * 8);
        cp16(sb + 8192 + u * 16, Bg + u * 8);
    }
    asm volatile("cp.async.commit_group;\n");

    for (int kt = 0; kt < NKT; kt++) {
        int buf = kt & 1;
        if (kt + 1 < NKT) {
            unsigned bo = (unsigned)((buf ^ 1) * 16384);
            const __half* An = Ag + (size_t)(kt + 1) * HBLK;
            const __half* Bn = Bg + (size_t)(kt + 1) * HBLK;
#pragma unroll
            for (int it = 0; it < 2; it++) {
                int u = tid + it * 256;
                cp16(sb + bo + u * 16, An + u * 8);
                cp16(sb + bo + 8192 + u * 16, Bn + u * 8);
            }
            asm volatile("cp.async.commit_group;\n");
            asm volatile("cp.async.wait_group 1;\n");
        } else {
            asm volatile("cp.async.wait_group 0;\n");
        }
        __syncthreads();

        const uint4* As4 = (const uint4*)(smc + buf * 16384);
        const uint4* Bs4 = (const uint4*)(smc + buf * 16384 + 8192);
#pragma unroll
        for (int ks = 0; ks < 2; ks++) {
            uint4 af[4], bf[2];
#pragma unroll
            for (int mi = 0; mi < 4; mi++)
                af[mi] = As4[(ks * 8 + wmSel * 4 + mi) * 32 + lane];
#pragma unroll
            for (int nip = 0; nip < 2; nip++)
                bf[nip] = Bs4[(ks * 8 + wnSel * 2 + nip) * 32 + lane];
#pragma unroll
            for (int mi = 0; mi < 4; mi++)
#pragma unroll
                for (int nip = 0; nip < 2; nip++) {
                    mma16(acc[mi][2 * nip],     (const unsigned*)&af[mi], bf[nip].x, bf[nip].y);
                    mma16(acc[mi][2 * nip + 1], (const unsigned*)&af[mi], bf[nip].z, bf[nip].w);
                }
        }
        __syncthreads();
    }

    const int wm = wmSel * 64;
    const int wn = wnSel * 32;
#pragma unroll
    for (int mi = 0; mi < 4; mi++) {
        int r = bm + wm + mi * 16 + gID;
#pragma unroll
        for (int ni = 0; ni < 4; ni++) {
            int c = bn + wn + ni * 8 + 2 * tig;
            float2 bv = *(const float2*)(bias + c);
            float o0 = acc[mi][ni][0] + bv.x, o1 = acc[mi][ni][1] + bv.y;
            float o2 = acc[mi][ni][2] + bv.x, o3 = acc[mi][ni][3] + bv.y;
            if (HALF_OUT) {
                __half* Ch = (__half*)C;
                *(__half2*)(Ch + (size_t)r * N + c)       = __floats2half2_rn(o0, o1);
                *(__half2*)(Ch + (size_t)(r + 8) * N + c) = __floats2half2_rn(o2, o3);
            } else {
                float* Cf = (float*)C;
                *(float2*)(Cf + (size_t)r * N + c)       = make_float2(o0, o1);
                *(float2*)(Cf + (size_t)(r + 8) * N + c) = make_float2(o2, o3);
            }
        }
    }
}

// Fused QKV projection: bx 0..15 -> Q, 16..19 -> K, 20..23 -> V
__global__ __launch_bounds__(256, 2)
void qkv_fp16()
{
    __shared__ char smc[GEMM16_SMEM];
    int bx = blockIdx.x, rt = blockIdx.y;
    const __half *B; __half* C; const float* bias; int N, nt;
    if (bx < 16)      { B = g_wqf; C = g_qh; bias = g_bq; N = QINNER;  nt = bx; }
    else if (bx < 20) { B = g_wkf; C = g_kh; bias = g_bk; N = KVINNER; nt = bx - 16; }
    else              { B = g_wvf; C = g_vh; bias = g_bv; N = KVINNER; nt = bx - 20; }
    gemm16_body<true>(g_xf + (size_t)rt * NKT * HBLK, B + (size_t)nt * NKT * HBLK,
                      bias, C, N, rt * 128, nt * 128, smc);
}

__global__ __launch_bounds__(256, 2)
void oproj_fp16(const float* __restrict__ bo, float* __restrict__ C)
{
    __shared__ char smc[GEMM16_SMEM];
    int nt = blockIdx.x, rt = blockIdx.y;
    gemm16_body<false>(g_attf + (size_t)rt * NKT * HBLK, g_wof + (size_t)nt * NKT * HBLK,
                       bo, C, DMODEL, rt * 128, nt * 128, smc);
}

__global__ void set_bias(const float* bq, const float* bk, const float* bv)
{
    if (threadIdx.x == 0) { g_bq = bq; g_bk = bk; g_bv = bv; }
}

// ---------------------------------------------------------------------------
// fp16 flash attention (m16n8k16). K/V pre-packed; double-buffered cp.async.
// Epilogue writes att directly into fragment-major fp16 blocks (g_attf).
// ---------------------------------------------------------------------------
#define ABQ   64
#define ABK   64
#define ATHR  128
#define PPADH 72
#define TILE_H 8192
#define SMEM_ATTN (4 * 16384 + ABQ * PPADH * 2)

__global__ __launch_bounds__(ATHR, 2)
void attn_fp16(const int* __restrict__ mask)
{
    extern __shared__ char smc[];
    const unsigned kfs = (unsigned)__cvta_generic_to_shared(smc);
    const unsigned vfs = kfs + 32768;
    __half* Ps = (__half*)(smc + 65536);

    const int tid  = threadIdx.x;
    const int lane = tid & 31;
    const int wid  = tid >> 5;
    const int gID  = lane >> 2;
    const int tig  = lane & 3;
    const int q0   = blockIdx.x * ABQ;
    const int bh   = blockIdx.y;
    const int b    = bh >> 4;
    const int h    = bh & 15;
    const int kh   = h >> 2;
    const float scale = 0.08838834764831845f;

    const __half* kblk0 = g_kf16 + ((size_t)(b * NKV + kh) * NTILE) * TILE_H;
    const __half* vblk0 = g_vf16 + ((size_t)(b * NKV + kh) * NTILE) * TILE_H;

    const int qr0 = q0 + wid * 16 + gID;
    const unsigned* qb0 = (const unsigned*)(g_qh + (size_t)(b * SEQ + qr0) * QINNER + h * DHEAD);
    const unsigned* qb1 = qb0 + 8 * QINNER / 2;
    unsigned qa[8][4];
#pragma unroll
    for (int ks = 0; ks < 8; ks++) {
        qa[ks][0] = qb0[8 * ks + tig];
        qa[ks][1] = qb1[8 * ks + tig];
        qa[ks][2] = qb0[8 * ks + tig + 4];
        qa[ks][3] = qb1[8 * ks + tig + 4];
    }

    float o[16][4];
#pragma unroll
    for (int n = 0; n < 16; n++)
#pragma unroll
        for (int j = 0; j < 4; j++) o[n][j] = 0.f;
    float m0 = -1e30f, m1 = -1e30f, l0 = 0.f, l1 = 0.f;

    const int* mrow0 = mask + (size_t)b * SEQ * SEQ + (size_t)qr0 * SEQ;
    const int* mrow1 = mrow0 + 8 * SEQ;

    __half* prow0 = Ps + (wid * 16 + gID) * PPADH;
    __half* prow1 = prow0 + 8 * PPADH;

#pragma unroll
    for (int it = 0; it < 8; it++) {
        int u = tid + it * ATHR;
        cp16(kfs + u * 16, kblk0 + u * 8);
        cp16(vfs + u * 16, vblk0 + u * 8);
    }
    asm volatile("cp.async.commit_group;\n");

    for (int t = 0; t < NTILE; t++) {
        int buf = t & 1;
        if (t + 1 < NTILE) {
            int bn = buf ^ 1;
            const __half* kb = kblk0 + (size_t)(t + 1) * TILE_H;
            const __half* vb = vblk0 + (size_t)(t + 1) * TILE_H;
#pragma unroll
            for (int it = 0; it < 8; it++) {
                int u = tid + it * ATHR;
                cp16(kfs + bn * 16384 + u * 16, kb + u * 8);
                cp16(vfs + bn * 16384 + u * 16, vb + u * 8);
            }
            asm volatile("cp.async.commit_group;\n");
            asm volatile("cp.async.wait_group 1;\n");
        } else {
            asm volatile("cp.async.wait_group 0;\n");
        }
        __syncthreads();

        const uint4* Kf = (const uint4*)(smc + buf * 16384);
        const uint4* Vf = (const uint4*)(smc + 32768 + buf * 16384);
        const int k0 = t * ABK;

        float s[8][4];
#pragma unroll
        for (int ni = 0; ni < 8; ni++)
#pragma unroll
            for (int j = 0; j < 4; j++) s[ni][j] = 0.f;

#pragma unroll
        for (int ks = 0; ks < 8; ks++) {
#pragma unroll
            for (int nip = 0; nip < 4; nip++) {
                uint4 kf = Kf[(ks * 4 + nip) * 32 + lane];
                mma16(s[2 * nip],     qa[ks], kf.x, kf.y);
                mma16(s[2 * nip + 1], qa[ks], kf.z, kf.w);
            }
        }

        float nm0 = m0, nm1 = m1;
#pragma unroll
        for (int ni = 0; ni < 8; ni++) {
            int cc = k0 + ni * 8 + 2 * tig;
            int2 mm0 = *(const int2*)(mrow0 + cc);
            int2 mm1 = *(const int2*)(mrow1 + cc);
            s[ni][0] = mm0.x ? s[ni][0] * scale : -1e30f;
            s[ni][1] = mm0.y ? s[ni][1] * scale : -1e30f;
            s[ni][2] = mm1.x ? s[ni][2] * scale : -1e30f;
            s[ni][3] = mm1.y ? s[ni][3] * scale : -1e30f;
            nm0 = fmaxf(nm0, fmaxf(s[ni][0], s[ni][1]));
            nm1 = fmaxf(nm1, fmaxf(s[ni][2], s[ni][3]));
        }
        nm0 = fmaxf(nm0, __shfl_xor_sync(0xffffffffu, nm0, 1));
        nm0 = fmaxf(nm0, __shfl_xor_sync(0xffffffffu, nm0, 2));
        nm1 = fmaxf(nm1, __shfl_xor_sync(0xffffffffu, nm1, 1));
        nm1 = fmaxf(nm1, __shfl_xor_sync(0xffffffffu, nm1, 2));

        float corr0 = __expf(m0 - nm0);
        float corr1 = __expf(m1 - nm1);
        m0 = nm0; m1 = nm1;

        float rs0 = 0.f, rs1 = 0.f;
#pragma unroll
        for (int ni = 0; ni < 8; ni++) {
            s[ni][0] = (s[ni][0] > -1e29f) ? __expf(s[ni][0] - m0) : 0.f;
            s[ni][1] = (s[ni][1] > -1e29f) ? __expf(s[ni][1] - m0) : 0.f;
            s[ni][2] = (s[ni][2] > -1e29f) ? __expf(s[ni][2] - m1) : 0.f;
            s[ni][3] = (s[ni][3] > -1e29f) ? __expf(s[ni][3] - m1) : 0.f;
            rs0 += s[ni][0] + s[ni][1];
            rs1 += s[ni][2] + s[ni][3];
        }
        rs0 += __shfl_xor_sync(0xffffffffu, rs0, 1);
        rs0 += __shfl_xor_sync(0xffffffffu, rs0, 2);
        rs1 += __shfl_xor_sync(0xffffffffu, rs1, 1);
        rs1 += __shfl_xor_sync(0xffffffffu, rs1, 2);
        l0 = l0 * corr0 + rs0;
        l1 = l1 * corr1 + rs1;

#pragma unroll
        for (int n = 0; n < 16; n++) {
            o[n][0] *= corr0; o[n][1] *= corr0;
            o[n][2] *= corr1; o[n][3] *= corr1;
        }

#pragma unroll
        for (int ni = 0; ni < 8; ni++) {
            *(__half2*)(prow0 + ni * 8 + 2 * tig) = __floats2half2_rn(s[ni][0], s[ni][1]);
            *(__half2*)(prow1 + ni * 8 + 2 * tig) = __floats2half2_rn(s[ni][2], s[ni][3]);
        }
        __syncwarp();

#pragma unroll
        for (int ks2 = 0; ks2 < 4; ks2++) {
            unsigned pa[4];
            pa[0] = *(const unsigned*)(prow0 + 16 * ks2 + 2 * tig);
            pa[1] = *(const unsigned*)(prow1 + 16 * ks2 + 2 * tig);
            pa[2] = *(const unsigned*)(prow0 + 16 * ks2 + 2 * tig + 8);
            pa[3] = *(const unsigned*)(prow1 + 16 * ks2 + 2 * tig + 8);
#pragma unroll
            for (int nip = 0; nip < 8; nip++) {
                uint4 vf = Vf[(ks2 * 8 + nip) * 32 + lane];
                mma16(o[2 * nip],     pa, vf.x, vf.y);
                mma16(o[2 * nip + 1], pa, vf.z, vf.w);
            }
        }
        __syncthreads();
    }

    // ---- normalize + store att in fragment-major fp16 blocks ----
    float inv0 = (l0 > 0.f) ? (1.f / l0) : 0.f;
    float inv1 = (l1 > 0.f) ? (1.f / l1) : 0.f;
    int rr = (b * SEQ + qr0) & 127;
    int mi = rr >> 4;                       // rr&15 == gID+8*hsel handled below
    size_t rowblk = (size_t)((b * SEQ + qr0) >> 7) * NKT;
    unsigned short* attf = (unsigned short*)g_attf;
#pragma unroll
    for (int ni = 0; ni < 16; ni++) {
        int c    = h * DHEAD + ni * 8 + 2 * tig;
        int kt   = c >> 5;
        int ks   = (ni & 3) >> 1;
        int breg = ni & 1;
        unsigned short* base = attf + (rowblk + kt) * HBLK
            + ((ks * 8 + mi) * 32 + gID * 4 + tig) * 8 + (breg << 1) * 2;
        *(unsigned*)(base)     = pack2h(o[ni][0] * inv0, o[ni][1] * inv0);  // row qr0   (areg=2breg)
        *(unsigned*)(base + 2) = pack2h(o[ni][2] * inv1, o[ni][3] * inv1);  // row qr0+8 (areg=2breg+1)
    }
}

// ---------------------------------------------------------------------------
// Launch
// ---------------------------------------------------------------------------
extern "C" void kernel_launch(void* const* d_in, const int* in_sizes, int n_in,
                              void* d_out, int out_size)
{
    const float* x    = (const float*)d_in[0];
    const int*   mask = (const int*)  d_in[1];
    const float* Wq   = (const float*)d_in[2];
    const float* bq   = (const float*)d_in[3];
    const float* Wk   = (const float*)d_in[4];
    const float* bk   = (const float*)d_in[5];
    const float* Wv   = (const float*)d_in[6];
    const float* bv   = (const float*)d_in[7];
    const float* Wo   = (const float*)d_in[8];
    const float* bo   = (const float*)d_in[9];
    float* out = (float*)d_out;

    cudaFuncSetAttribute(attn_fp16, cudaFuncAttributeMaxDynamicSharedMemorySize, SMEM_ATTN);

    dim3 thr(256);
    set_bias<<<1, 32>>>(bq, bk, bv);
    pack_all<<<(GALL + 255) / 256, thr>>>(
        (const float4*)x, (const float4*)Wq, (const float4*)Wk,
        (const float4*)Wv, (const float4*)Wo);
    qkv_fp16<<<dim3(24, MROWS / 128), thr>>>();
    kv_pack<<<(BB * NKV * SEQ * 32) / 256, thr>>>();
    attn_fp16<<<dim3(SEQ / ABQ, BB * NHEAD), dim3(ATHR), SMEM_ATTN>>>(mask);
    oproj_fp16<<<dim3(DMODEL / 128, MROWS / 128), thr>>>(bo, out);
}

// round 15
// speedup vs baseline: 2.2567x; 1.0541x over previous
#include <cuda_runtime.h>
#include <cuda_fp16.h>
#include <math.h>

// ---------------------------------------------------------------------------
// Problem constants
// ---------------------------------------------------------------------------
#define BB      2
#define SEQ     2048
#define DMODEL  2048
#define NHEAD   16
#define NKV     4
#define DHEAD   128
#define QINNER  (NHEAD * DHEAD)    // 2048
#define KVINNER (NKV * DHEAD)      // 512
#define NREP    (NHEAD / NKV)      // 4
#define MROWS   (BB * SEQ)         // 4096
#define NTILE   (SEQ / 64)         // 32 KV tiles per (b,kh)
#define NKT     (DMODEL / 32)      // 64 k-tiles (K=2048 for all GEMMs)
#define HBLK    4096               // halves per 128x32 fragment block (8KB)

// Scratch (allocation-free rule: device globals)
__device__ __half g_qh[MROWS * QINNER];    // fp16 q, linear (qkv epilogue)
__device__ __half g_kh[MROWS * KVINNER];   // fp16 k, linear
__device__ __half g_vh[MROWS * KVINNER];   // fp16 v, linear
// fragment-major fp16 operands for GEMMs (blocks of 128x32 = 4096 halves)
__device__ __half g_xf [32 * NKT * HBLK];  // X  [rt=32][kt=64]
__device__ __half g_wqf[16 * NKT * HBLK];  // Wq [nt=16][kt]
__device__ __half g_wkf[ 4 * NKT * HBLK];  // Wk [nt=4]
__device__ __half g_wvf[ 4 * NKT * HBLK];  // Wv
__device__ __half g_wof[16 * NKT * HBLK];  // Wo [nt=16]
__device__ __half g_attf[32 * NKT * HBLK]; // att [rt=32][kt] (attn epilogue)
// K/V in fp16 m16n8k16 fragment-major attention tiles
__device__ __half g_kf16[BB * NKV * NTILE * 8192];
__device__ __half g_vf16[BB * NKV * NTILE * 8192];
// mask packed to 1 bit/element: [b][q][k/32]
#define MWORDS (BB * SEQ * (SEQ / 32))     // 262144 words = 1MB
__device__ unsigned g_mbits[MWORDS];

// bias pointers for the fused qkv kernel
__device__ const float* g_bq;
__device__ const float* g_bk;
__device__ const float* g_bv;

// ---------------------------------------------------------------------------
// helpers
// ---------------------------------------------------------------------------
// fp16: D(16x8,f32) += A(16x16,f16) * B(16x8,f16)
__device__ __forceinline__ void mma16(float* d, const unsigned* a, unsigned b0, unsigned b1) {
    asm("mma.sync.aligned.m16n8k16.row.col.f32.f16.f16.f32 "
        "{%0,%1,%2,%3},{%4,%5,%6,%7},{%8,%9},{%0,%1,%2,%3};"
        : "+f"(d[0]), "+f"(d[1]), "+f"(d[2]), "+f"(d[3])
        : "r"(a[0]), "r"(a[1]), "r"(a[2]), "r"(a[3]), "r"(b0), "r"(b1));
}

__device__ __forceinline__ void cp16(unsigned s, const void* g) {
    asm volatile("cp.async.cg.shared.global [%0], [%1], 16;\n" :: "r"(s), "l"(g));
}

__device__ __forceinline__ unsigned pack2h(float a, float b) {
    __half2 h = __floats2half2_rn(a, b);
    return *(unsigned*)&h;
}

// ---------------------------------------------------------------------------
// mask_pack: 32 mask ints -> 1 bit word
// ---------------------------------------------------------------------------
__global__ __launch_bounds__(256)
void mask_pack(const int4* __restrict__ mask)
{
    int i = blockIdx.x * 256 + threadIdx.x;
    if (i >= MWORDS) return;
    const int4* src = mask + (size_t)i * 8;
    unsigned bits = 0;
#pragma unroll
    for (int j = 0; j < 8; j++) {
        int4 v = src[j];
        bits |= (v.x ? 1u : 0u) << (j * 4)
             |  (v.y ? 1u : 0u) << (j * 4 + 1)
             |  (v.z ? 1u : 0u) << (j * 4 + 2)
             |  (v.w ? 1u : 0u) << (j * 4 + 3);
    }
    g_mbits[i] = bits;
}

// ---------------------------------------------------------------------------
// pack_all: convert fp32 inputs to fp16 and permute into fragment-major
// 128x32 blocks.  A-layout (m-major operand), B-layout (n-major operand).
// ---------------------------------------------------------------------------
__device__ __forceinline__
void pack_a4(unsigned short* dst, float4 v, int r, int k0)
{
    unsigned p0 = pack2h(v.x, v.y), p1 = pack2h(v.z, v.w);
    int rt = r >> 7, rr = r & 127, kt = k0 >> 5, kk = k0 & 31;
    int ks = kk >> 4, kkk = kk & 15;
    int mi = rr >> 4, gID = rr & 7, hsel = (rr >> 3) & 1;
    int tigA = (kkk & 7) >> 1, breg = kkk >> 3;
    int areg = (breg << 1) | hsel;
    unsigned short* b = dst + (size_t)(rt * NKT + kt) * HBLK
                      + ((ks * 8 + mi) * 32 + gID * 4) * 8 + areg * 2;
    *(unsigned*)(b + tigA * 8)       = p0;
    *(unsigned*)(b + (tigA + 1) * 8) = p1;
}

__device__ __forceinline__
void pack_b4(unsigned short* dst, float4 v, int c, int k0)
{
    unsigned p0 = pack2h(v.x, v.y), p1 = pack2h(v.z, v.w);
    int nt = c >> 7, cc = c & 127, kt = k0 >> 5, kk = k0 & 31;
    int ks = kk >> 4, kkk = kk & 15;
    int nj = cc >> 3, gID = cc & 7;
    int u = ks * 8 + (nj >> 1);
    int w = ((nj & 1) << 1) | (kkk >> 3);
    int tig = (kkk & 7) >> 1;
    unsigned short* b = dst + (size_t)(nt * NKT + kt) * HBLK
                      + (u * 32 + gID * 4) * 8 + w * 2;
    *(unsigned*)(b + tig * 8)       = p0;
    *(unsigned*)(b + (tig + 1) * 8) = p1;
}

#define GX   (MROWS * 512)
#define GWQ  (QINNER * 512)
#define GWKV (KVINNER * 512)
#define GWO  (DMODEL * 512)
#define GALL (GX + GWQ + 2 * GWKV + GWO)

__global__ __launch_bounds__(256)
void pack_all(const float4* __restrict__ x,  const float4* __restrict__ wq,
              const float4* __restrict__ wk, const float4* __restrict__ wv,
              const float4* __restrict__ wo)
{
    int i = blockIdx.x * 256 + threadIdx.x;
    if (i >= GALL) return;
    if (i < GX) {
        int r = i >> 9, kg = i & 511;
        pack_a4((unsigned short*)g_xf, x[(size_t)r * 512 + kg], r, kg * 4);
    } else if (i < GX + GWQ) {
        int j = i - GX; int c = j >> 9, kg = j & 511;
        pack_b4((unsigned short*)g_wqf, wq[(size_t)c * 512 + kg], c, kg * 4);
    } else if (i < GX + GWQ + GWKV) {
        int j = i - GX - GWQ; int c = j >> 9, kg = j & 511;
        pack_b4((unsigned short*)g_wkf, wk[(size_t)c * 512 + kg], c, kg * 4);
    } else if (i < GX + GWQ + 2 * GWKV) {
        int j = i - GX - GWQ - GWKV; int c = j >> 9, kg = j & 511;
        pack_b4((unsigned short*)g_wvf, wv[(size_t)c * 512 + kg], c, kg * 4);
    } else {
        int j = i - GX - GWQ - 2 * GWKV; int c = j >> 9, kg = j & 511;
        pack_b4((unsigned short*)g_wof, wo[(size_t)c * 512 + kg], c, kg * 4);
    }
}

// ---------------------------------------------------------------------------
// kv_pack: permute fp16 K/V into m16n8k16 attention fragment tiles (pure bits).
// ---------------------------------------------------------------------------
__global__ __launch_bounds__(256)
void kv_pack()
{
    int gidx  = blockIdx.x * 256 + threadIdx.x;
    int lane  = gidx & 31;
    int s_lin = gidx >> 5;
    int s  = s_lin & (SEQ - 1);
    int bk = s_lin >> 11;
    int b  = bk >> 2;
    int kh = bk & 3;

    size_t goff = (size_t)(b * SEQ + s) * KVINNER + kh * DHEAD + lane * 4;
    union { uint2 u; unsigned short h[4]; } ku, vu;
    ku.u = *(const uint2*)(g_kh + goff);
    vu.u = *(const uint2*)(g_vh + goff);

    int r = s & 63;
    int t = s >> 6;
    size_t tb = ((size_t)(b * NKV + kh) * NTILE + t) << 13;
    unsigned short* kdst = (unsigned short*)g_kf16 + tb;
    unsigned short* vdst = (unsigned short*)g_vf16 + tb;

    int d0 = lane * 4;
    {
        int ks = d0 >> 4, dd0 = d0 & 15;
        int breg = (dd0 >> 3) & 1;
        int ni = r >> 3, gK = r & 7;
        int w2 = (((ni & 1) << 1) | breg) << 1;
        int u4 = ((ks * 4 + (ni >> 1)) * 32 + gK * 4) * 8;
        int tigA = (dd0 & 7) >> 1;
        unsigned p0 = (unsigned)ku.h[0] | ((unsigned)ku.h[1] << 16);
        unsigned p1 = (unsigned)ku.h[2] | ((unsigned)ku.h[3] << 16);
        *(unsigned*)(kdst + u4 + tigA * 8 + w2)       = p0;
        *(unsigned*)(kdst + u4 + (tigA + 1) * 8 + w2) = p1;
    }
    {
        int ks2 = r >> 4, kk = r & 15;
        int breg = (kk >> 3) & 1;
        int tigv = (kk & 7) >> 1;
        int hp = kk & 1;
        int ni = d0 >> 3;
        int w2hp = ((((ni & 1) << 1) | breg) << 1) + hp;
        int base = (ks2 * 8 + (ni >> 1)) * 32 * 8 + tigv * 8 + w2hp;
#pragma unroll
        for (int j = 0; j < 4; j++) {
            int gV = (d0 & 7) + j;
            vdst[base + gV * 32] = vu.h[j];
        }
    }
}

// ---------------------------------------------------------------------------
// fp16 GEMM: operands pre-packed fragment-major; 3-stage cp.async pipeline.
// 128x128x32 tiles, 8 warps (2 wm x 4 wn), warp 64x32 via m16n8k16.
// ---------------------------------------------------------------------------
#define GSTAGE 3
#define GEMM16_SMEM (GSTAGE * 16384)   // 48KB

template<bool HALF_OUT>
__device__ __forceinline__
void gemm16_body(const __half* __restrict__ Ag, const __half* __restrict__ Bg,
                 const float* __restrict__ bias, void* __restrict__ C,
                 int N, int bm, int bn, char* smc)
{
    const int tid   = threadIdx.x;
    const int lane  = tid & 31;
    const int wid   = tid >> 5;
    const int gID   = lane >> 2;
    const int tig   = lane & 3;
    const int wmSel = wid & 1;
    const int wnSel = wid >> 1;
    const unsigned sb = (unsigned)__cvta_generic_to_shared(smc);

    float acc[4][4][4];
#pragma unroll
    for (int mi = 0; mi < 4; mi++)
#pragma unroll
        for (int ni = 0; ni < 4; ni++)
#pragma unroll
            for (int j = 0; j < 4; j++) acc[mi][ni][j] = 0.f;

    // prefetch tiles 0,1 into buffers 0,1
#pragma unroll
    for (int p = 0; p < 2; p++) {
        unsigned bo = (unsigned)(p * 16384);
        const __half* Ap = Ag + (size_t)p * HBLK;
        const __half* Bp = Bg + (size_t)p * HBLK;
#pragma unroll
        for (int it = 0; it < 2; it++) {
            int u = tid + it * 256;
            cp16(sb + bo + u * 16, Ap + u * 8);
            cp16(sb + bo + 8192 + u * 16, Bp + u * 8);
        }
        asm volatile("cp.async.commit_group;\n");
    }

    for (int kt = 0; kt < NKT; kt++) {
        int buf = kt % GSTAGE;
        if (kt + 2 < NKT) {
            unsigned bo = (unsigned)(((kt + 2) % GSTAGE) * 16384);
            const __half* An = Ag + (size_t)(kt + 2) * HBLK;
            const __half* Bn = Bg + (size_t)(kt + 2) * HBLK;
#pragma unroll
            for (int it = 0; it < 2; it++) {
                int u = tid + it * 256;
                cp16(sb + bo + u * 16, An + u * 8);
                cp16(sb + bo + 8192 + u * 16, Bn + u * 8);
            }
            asm volatile("cp.async.commit_group;\n");
            asm volatile("cp.async.wait_group 2;\n");
        } else if (kt + 1 < NKT) {
            asm volatile("cp.async.wait_group 1;\n");
        } else {
            asm volatile("cp.async.wait_group 0;\n");
        }
        __syncthreads();

        const uint4* As4 = (const uint4*)(smc + buf * 16384);
        const uint4* Bs4 = (const uint4*)(smc + buf * 16384 + 8192);
#pragma unroll
        for (int ks = 0; ks < 2; ks++) {
            uint4 af[4], bf[2];
#pragma unroll
            for (int mi = 0; mi < 4; mi++)
                af[mi] = As4[(ks * 8 + wmSel * 4 + mi) * 32 + lane];
#pragma unroll
            for (int nip = 0; nip < 2; nip++)
                bf[nip] = Bs4[(ks * 8 + wnSel * 2 + nip) * 32 + lane];
#pragma unroll
            for (int mi = 0; mi < 4; mi++)
#pragma unroll
                for (int nip = 0; nip < 2; nip++) {
                    mma16(acc[mi][2 * nip],     (const unsigned*)&af[mi], bf[nip].x, bf[nip].y);
                    mma16(acc[mi][2 * nip + 1], (const unsigned*)&af[mi], bf[nip].z, bf[nip].w);
                }
        }
        __syncthreads();
    }

    const int wm = wmSel * 64;
    const int wn = wnSel * 32;
#pragma unroll
    for (int mi = 0; mi < 4; mi++) {
        int r = bm + wm + mi * 16 + gID;
#pragma unroll
        for (int ni = 0; ni < 4; ni++) {
            int c = bn + wn + ni * 8 + 2 * tig;
            float2 bv = *(const float2*)(bias + c);
            float o0 = acc[mi][ni][0] + bv.x, o1 = acc[mi][ni][1] + bv.y;
            float o2 = acc[mi][ni][2] + bv.x, o3 = acc[mi][ni][3] + bv.y;
            if (HALF_OUT) {
                __half* Ch = (__half*)C;
                *(__half2*)(Ch + (size_t)r * N + c)       = __floats2half2_rn(o0, o1);
                *(__half2*)(Ch + (size_t)(r + 8) * N + c) = __floats2half2_rn(o2, o3);
            } else {
                float* Cf = (float*)C;
                *(float2*)(Cf + (size_t)r * N + c)       = make_float2(o0, o1);
                *(float2*)(Cf + (size_t)(r + 8) * N + c) = make_float2(o2, o3);
            }
        }
    }
}

// Fused QKV projection: bx 0..15 -> Q, 16..19 -> K, 20..23 -> V
__global__ __launch_bounds__(256, 2)
void qkv_fp16()
{
    __shared__ char smc[GEMM16_SMEM];
    int bx = blockIdx.x, rt = blockIdx.y;
    const __half *B; __half* C; const float* bias; int N, nt;
    if (bx < 16)      { B = g_wqf; C = g_qh; bias = g_bq; N = QINNER;  nt = bx; }
    else if (bx < 20) { B = g_wkf; C = g_kh; bias = g_bk; N = KVINNER; nt = bx - 16; }
    else              { B = g_wvf; C = g_vh; bias = g_bv; N = KVINNER; nt = bx - 20; }
    gemm16_body<true>(g_xf + (size_t)rt * NKT * HBLK, B + (size_t)nt * NKT * HBLK,
                      bias, C, N, rt * 128, nt * 128, smc);
}

__global__ __launch_bounds__(256, 2)
void oproj_fp16(const float* __restrict__ bo, float* __restrict__ C)
{
    __shared__ char smc[GEMM16_SMEM];
    int nt = blockIdx.x, rt = blockIdx.y;
    gemm16_body<false>(g_attf + (size_t)rt * NKT * HBLK, g_wof + (size_t)nt * NKT * HBLK,
                       bo, C, DMODEL, rt * 128, nt * 128, smc);
}

__global__ void set_bias(const float* bq, const float* bk, const float* bv)
{
    if (threadIdx.x == 0) { g_bq = bq; g_bk = bk; g_bv = bv; }
}

// ---------------------------------------------------------------------------
// fp16 flash attention (m16n8k16). K/V pre-packed; double-buffered cp.async;
// bitmask mask with all-ones fast path. ABQ=64, 4 warps, 2 CTAs/SM.
// ---------------------------------------------------------------------------
#define ABQ   64
#define ABK   64
#define ATHR  128
#define PPADH 72
#define TILE_H 8192
#define SMEM_ATTN (4 * 16384 + ABQ * PPADH * 2)

__global__ __launch_bounds__(ATHR, 2)
void attn_fp16()
{
    extern __shared__ char smc[];
    const unsigned kfs = (unsigned)__cvta_generic_to_shared(smc);
    const unsigned vfs = kfs + 32768;
    __half* Ps = (__half*)(smc + 65536);

    const int tid  = threadIdx.x;
    const int lane = tid & 31;
    const int wid  = tid >> 5;
    const int gID  = lane >> 2;
    const int tig  = lane & 3;
    const int q0   = blockIdx.x * ABQ;
    const int bh   = blockIdx.y;
    const int b    = bh >> 4;
    const int h    = bh & 15;
    const int kh   = h >> 2;
    const float scale = 0.08838834764831845f;

    const __half* kblk0 = g_kf16 + ((size_t)(b * NKV + kh) * NTILE) * TILE_H;
    const __half* vblk0 = g_vf16 + ((size_t)(b * NKV + kh) * NTILE) * TILE_H;

    const int qr0 = q0 + wid * 16 + gID;
    const unsigned* qb0 = (const unsigned*)(g_qh + (size_t)(b * SEQ + qr0) * QINNER + h * DHEAD);
    const unsigned* qb1 = qb0 + 8 * QINNER / 2;
    unsigned qa[8][4];
#pragma unroll
    for (int ks = 0; ks < 8; ks++) {
        qa[ks][0] = qb0[8 * ks + tig];
        qa[ks][1] = qb1[8 * ks + tig];
        qa[ks][2] = qb0[8 * ks + tig + 4];
        qa[ks][3] = qb1[8 * ks + tig + 4];
    }

    float o[16][4];
#pragma unroll
    for (int n = 0; n < 16; n++)
#pragma unroll
        for (int j = 0; j < 4; j++) o[n][j] = 0.f;
    float m0 = -1e30f, m1 = -1e30f, l0 = 0.f, l1 = 0.f;

    const unsigned* mb0 = g_mbits + ((size_t)(b * SEQ) + qr0) * (SEQ / 32);
    const unsigned* mb1 = mb0 + 8 * (SEQ / 32);

    __half* prow0 = Ps + (wid * 16 + gID) * PPADH;
    __half* prow1 = prow0 + 8 * PPADH;

#pragma unroll
    for (int it = 0; it < 8; it++) {
        int u = tid + it * ATHR;
        cp16(kfs + u * 16, kblk0 + u * 8);
        cp16(vfs + u * 16, vblk0 + u * 8);
    }
    asm volatile("cp.async.commit_group;\n");

    for (int t = 0; t < NTILE; t++) {
        int buf = t & 1;
        if (t + 1 < NTILE) {
            int bn = buf ^ 1;
            const __half* kb = kblk0 + (size_t)(t + 1) * TILE_H;
            const __half* vb = vblk0 + (size_t)(t + 1) * TILE_H;
#pragma unroll
            for (int it = 0; it < 8; it++) {
                int u = tid + it * ATHR;
                cp16(kfs + bn * 16384 + u * 16, kb + u * 8);
                cp16(vfs + bn * 16384 + u * 16, vb + u * 8);
            }
            asm volatile("cp.async.commit_group;\n");
            asm volatile("cp.async.wait_group 1;\n");
        } else {
            asm volatile("cp.async.wait_group 0;\n");
        }
        __syncthreads();

        const uint4* Kf = (const uint4*)(smc + buf * 16384);
        const uint4* Vf = (const uint4*)(smc + 32768 + buf * 16384);

        float s[8][4];
#pragma unroll
        for (int ni = 0; ni < 8; ni++)
#pragma unroll
            for (int j = 0; j < 4; j++) s[ni][j] = 0.f;

#pragma unroll
        for (int ks = 0; ks < 8; ks++) {
#pragma unroll
            for (int nip = 0; nip < 4; nip++) {
                uint4 kf = Kf[(ks * 4 + nip) * 32 + lane];
                mma16(s[2 * nip],     qa[ks], kf.x, kf.y);
                mma16(s[2 * nip + 1], qa[ks], kf.z, kf.w);
            }
        }

        // ---- scale + mask (bitmask, all-ones fast path) + online softmax ----
        uint2 w0 = *(const uint2*)(mb0 + t * 2);
        uint2 w1 = *(const uint2*)(mb1 + t * 2);
        unsigned long long M0 = ((unsigned long long)w0.y << 32) | w0.x;
        unsigned long long M1 = ((unsigned long long)w1.y << 32) | w1.x;

        float nm0 = m0, nm1 = m1;
        if ((M0 & M1) == 0xFFFFFFFFFFFFFFFFull) {
#pragma unroll
            for (int ni = 0; ni < 8; ni++) {
                s[ni][0] *= scale; s[ni][1] *= scale;
                s[ni][2] *= scale; s[ni][3] *= scale;
                nm0 = fmaxf(nm0, fmaxf(s[ni][0], s[ni][1]));
                nm1 = fmaxf(nm1, fmaxf(s[ni][2], s[ni][3]));
            }
        } else {
#pragma unroll
            for (int ni = 0; ni < 8; ni++) {
                int p = ni * 8 + 2 * tig;
                s[ni][0] = ((M0 >> p) & 1)       ? s[ni][0] * scale : -1e30f;
                s[ni][1] = ((M0 >> (p + 1)) & 1) ? s[ni][1] * scale : -1e30f;
                s[ni][2] = ((M1 >> p) & 1)       ? s[ni][2] * scale : -1e30f;
                s[ni][3] = ((M1 >> (p + 1)) & 1) ? s[ni][3] * scale : -1e30f;
                nm0 = fmaxf(nm0, fmaxf(s[ni][0], s[ni][1]));
                nm1 = fmaxf(nm1, fmaxf(s[ni][2], s[ni][3]));
            }
        }
        nm0 = fmaxf(nm0, __shfl_xor_sync(0xffffffffu, nm0, 1));
        nm0 = fmaxf(nm0, __shfl_xor_sync(0xffffffffu, nm0, 2));
        nm1 = fmaxf(nm1, __shfl_xor_sync(0xffffffffu, nm1, 1));
        nm1 = fmaxf(nm1, __shfl_xor_sync(0xffffffffu, nm1, 2));

        float corr0 = __expf(m0 - nm0);
        float corr1 = __expf(m1 - nm1);
        m0 = nm0; m1 = nm1;

        float rs0 = 0.f, rs1 = 0.f;
#pragma unroll
        for (int ni = 0; ni < 8; ni++) {
            s[ni][0] = (s[ni][0] > -1e29f) ? __expf(s[ni][0] - m0) : 0.f;
            s[ni][1] = (s[ni][1] > -1e29f) ? __expf(s[ni][1] - m0) : 0.f;
            s[ni][2] = (s[ni][2] > -1e29f) ? __expf(s[ni][2] - m1) : 0.f;
            s[ni][3] = (s[ni][3] > -1e29f) ? __expf(s[ni][3] - m1) : 0.f;
            rs0 += s[ni][0] + s[ni][1];
            rs1 += s[ni][2] + s[ni][3];
        }
        rs0 += __shfl_xor_sync(0xffffffffu, rs0, 1);
        rs0 += __shfl_xor_sync(0xffffffffu, rs0, 2);
        rs1 += __shfl_xor_sync(0xffffffffu, rs1, 1);
        rs1 += __shfl_xor_sync(0xffffffffu, rs1, 2);
        l0 = l0 * corr0 + rs0;
        l1 = l1 * corr1 + rs1;

#pragma unroll
        for (int n = 0; n < 16; n++) {
            o[n][0] *= corr0; o[n][1] *= corr0;
            o[n][2] *= corr1; o[n][3] *= corr1;
        }

#pragma unroll
        for (int ni = 0; ni < 8; ni++) {
            *(__half2*)(prow0 + ni * 8 + 2 * tig) = __floats2half2_rn(s[ni][0], s[ni][1]);
            *(__half2*)(prow1 + ni * 8 + 2 * tig) = __floats2half2_rn(s[ni][2], s[ni][3]);
        }
        __syncwarp();

#pragma unroll
        for (int ks2 = 0; ks2 < 4; ks2++) {
            unsigned pa[4];
            pa[0] = *(const unsigned*)(prow0 + 16 * ks2 + 2 * tig);
            pa[1] = *(const unsigned*)(prow1 + 16 * ks2 + 2 * tig);
            pa[2] = *(const unsigned*)(prow0 + 16 * ks2 + 2 * tig + 8);
            pa[3] = *(const unsigned*)(prow1 + 16 * ks2 + 2 * tig + 8);
#pragma unroll
            for (int nip = 0; nip < 8; nip++) {
                uint4 vf = Vf[(ks2 * 8 + nip) * 32 + lane];
                mma16(o[2 * nip],     pa, vf.x, vf.y);
                mma16(o[2 * nip + 1], pa, vf.z, vf.w);
            }
        }
        __syncthreads();
    }

    // ---- normalize + store att in fragment-major fp16 blocks ----
    float inv0 = (l0 > 0.f) ? (1.f / l0) : 0.f;
    float inv1 = (l1 > 0.f) ? (1.f / l1) : 0.f;
    int rr = (b * SEQ + qr0) & 127;
    int mi = rr >> 4;
    size_t rowblk = (size_t)((b * SEQ + qr0) >> 7) * NKT;
    unsigned short* attf = (unsigned short*)g_attf;
#pragma unroll
    for (int ni = 0; ni < 16; ni++) {
        int c    = h * DHEAD + ni * 8 + 2 * tig;
        int kt   = c >> 5;
        int ks   = (ni & 3) >> 1;
        int breg = ni & 1;
        unsigned short* base = attf + (rowblk + kt) * HBLK
            + ((ks * 8 + mi) * 32 + gID * 4 + tig) * 8 + (breg << 1) * 2;
        *(unsigned*)(base)     = pack2h(o[ni][0] * inv0, o[ni][1] * inv0);
        *(unsigned*)(base + 2) = pack2h(o[ni][2] * inv1, o[ni][3] * inv1);
    }
}

// ---------------------------------------------------------------------------
// Launch
// ---------------------------------------------------------------------------
extern "C" void kernel_launch(void* const* d_in, const int* in_sizes, int n_in,
                              void* d_out, int out_size)
{
    const float* x    = (const float*)d_in[0];
    const int*   mask = (const int*)  d_in[1];
    const float* Wq   = (const float*)d_in[2];
    const float* bq   = (const float*)d_in[3];
    const float* Wk   = (const float*)d_in[4];
    const float* bk   = (const float*)d_in[5];
    const float* Wv   = (const float*)d_in[6];
    const float* bv   = (const float*)d_in[7];
    const float* Wo   = (const float*)d_in[8];
    const float* bo   = (const float*)d_in[9];
    float* out = (float*)d_out;

    cudaFuncSetAttribute(attn_fp16, cudaFuncAttributeMaxDynamicSharedMemorySize, SMEM_ATTN);

    dim3 thr(256);
    set_bias<<<1, 32>>>(bq, bk, bv);
    mask_pack<<<(MWORDS + 255) / 256, thr>>>((const int4*)mask);
    pack_all<<<(GALL + 255) / 256, thr>>>(
        (const float4*)x, (const float4*)Wq, (const float4*)Wk,
        (const float4*)Wv, (const float4*)Wo);
    qkv_fp16<<<dim3(24, MROWS / 128), thr>>>();
    kv_pack<<<(BB * NKV * SEQ * 32) / 256, thr>>>();
    attn_fp16<<<dim3(SEQ / ABQ, BB * NHEAD), dim3(ATHR), SMEM_ATTN>>>();
    oproj_fp16<<<dim3(DMODEL / 128, MROWS / 128), thr>>>(bo, out);
}

// round 16
// speedup vs baseline: 2.4558x; 1.0882x over previous
#include <cuda_runtime.h>
#include <cuda_fp16.h>
#include <math.h>

// ---------------------------------------------------------------------------
// Problem constants
// ---------------------------------------------------------------------------
#define BB      2
#define SEQ     2048
#define DMODEL  2048
#define NHEAD   16
#define NKV     4
#define DHEAD   128
#define QINNER  (NHEAD * DHEAD)    // 2048
#define KVINNER (NKV * DHEAD)      // 512
#define NREP    (NHEAD / NKV)      // 4
#define MROWS   (BB * SEQ)         // 4096
#define NTILE   (SEQ / 64)         // 32 KV tiles per (b,kh)
#define NKT     (DMODEL / 32)      // 64 k-tiles (K=2048 for all GEMMs)
#define HBLK    4096               // halves per 128x32 fragment block (8KB)

// Scratch (allocation-free rule: device globals)
__device__ __half g_qh[MROWS * QINNER];    // fp16 q, linear (qkv epilogue)
__device__ __half g_kh[MROWS * KVINNER];   // fp16 k, linear
__device__ __half g_vh[MROWS * KVINNER];   // fp16 v, linear
// fragment-major fp16 operands for GEMMs (blocks of 128x32 = 4096 halves)
__device__ __half g_xf [32 * NKT * HBLK];  // X  [rt=32][kt=64]
__device__ __half g_wqf[16 * NKT * HBLK];  // Wq [nt=16][kt]
__device__ __half g_wkf[ 4 * NKT * HBLK];  // Wk [nt=4]
__device__ __half g_wvf[ 4 * NKT * HBLK];  // Wv
__device__ __half g_wof[16 * NKT * HBLK];  // Wo [nt=16]
__device__ __half g_attf[32 * NKT * HBLK]; // att [rt=32][kt] (attn epilogue)
// K/V in fp16 m16n8k16 fragment-major attention tiles
__device__ __half g_kf16[BB * NKV * NTILE * 8192];
__device__ __half g_vf16[BB * NKV * NTILE * 8192];
// mask packed to 1 bit/element: [b][q][k/32]
#define MWORDS (BB * SEQ * (SEQ / 32))     // 262144 words = 1MB
__device__ unsigned g_mbits[MWORDS];

// bias pointers for the fused qkv kernel
__device__ const float* g_bq;
__device__ const float* g_bk;
__device__ const float* g_bv;

// ---------------------------------------------------------------------------
// helpers
// ---------------------------------------------------------------------------
// fp16: D(16x8,f32) += A(16x16,f16) * B(16x8,f16)
__device__ __forceinline__ void mma16(float* d, const unsigned* a, unsigned b0, unsigned b1) {
    asm("mma.sync.aligned.m16n8k16.row.col.f32.f16.f16.f32 "
        "{%0,%1,%2,%3},{%4,%5,%6,%7},{%8,%9},{%0,%1,%2,%3};"
        : "+f"(d[0]), "+f"(d[1]), "+f"(d[2]), "+f"(d[3])
        : "r"(a[0]), "r"(a[1]), "r"(a[2]), "r"(a[3]), "r"(b0), "r"(b1));
}

__device__ __forceinline__ void cp16(unsigned s, const void* g) {
    asm volatile("cp.async.cg.shared.global [%0], [%1], 16;\n" :: "r"(s), "l"(g));
}

__device__ __forceinline__ unsigned pack2h(float a, float b) {
    __half2 h = __floats2half2_rn(a, b);
    return *(unsigned*)&h;
}

// ---------------------------------------------------------------------------
// mask_pack: 32 mask ints -> 1 bit word
// ---------------------------------------------------------------------------
__global__ __launch_bounds__(256)
void mask_pack(const int4* __restrict__ mask)
{
    int i = blockIdx.x * 256 + threadIdx.x;
    if (i >= MWORDS) return;
    const int4* src = mask + (size_t)i * 8;
    unsigned bits = 0;
#pragma unroll
    for (int j = 0; j < 8; j++) {
        int4 v = src[j];
        bits |= (v.x ? 1u : 0u) << (j * 4)
             |  (v.y ? 1u : 0u) << (j * 4 + 1)
             |  (v.z ? 1u : 0u) << (j * 4 + 2)
             |  (v.w ? 1u : 0u) << (j * 4 + 3);
    }
    g_mbits[i] = bits;
}

// ---------------------------------------------------------------------------
// pack_all: convert fp32 inputs to fp16 and permute into fragment-major
// 128x32 blocks.  A-layout (m-major operand), B-layout (n-major operand).
// ---------------------------------------------------------------------------
__device__ __forceinline__
void pack_a4(unsigned short* dst, float4 v, int r, int k0)
{
    unsigned p0 = pack2h(v.x, v.y), p1 = pack2h(v.z, v.w);
    int rt = r >> 7, rr = r & 127, kt = k0 >> 5, kk = k0 & 31;
    int ks = kk >> 4, kkk = kk & 15;
    int mi = rr >> 4, gID = rr & 7, hsel = (rr >> 3) & 1;
    int tigA = (kkk & 7) >> 1, breg = kkk >> 3;
    int areg = (breg << 1) | hsel;
    unsigned short* b = dst + (size_t)(rt * NKT + kt) * HBLK
                      + ((ks * 8 + mi) * 32 + gID * 4) * 8 + areg * 2;
    *(unsigned*)(b + tigA * 8)       = p0;
    *(unsigned*)(b + (tigA + 1) * 8) = p1;
}

__device__ __forceinline__
void pack_b4(unsigned short* dst, float4 v, int c, int k0)
{
    unsigned p0 = pack2h(v.x, v.y), p1 = pack2h(v.z, v.w);
    int nt = c >> 7, cc = c & 127, kt = k0 >> 5, kk = k0 & 31;
    int ks = kk >> 4, kkk = kk & 15;
    int nj = cc >> 3, gID = cc & 7;
    int u = ks * 8 + (nj >> 1);
    int w = ((nj & 1) << 1) | (kkk >> 3);
    int tig = (kkk & 7) >> 1;
    unsigned short* b = dst + (size_t)(nt * NKT + kt) * HBLK
                      + (u * 32 + gID * 4) * 8 + w * 2;
    *(unsigned*)(b + tig * 8)       = p0;
    *(unsigned*)(b + (tig + 1) * 8) = p1;
}

#define GX   (MROWS * 512)
#define GWQ  (QINNER * 512)
#define GWKV (KVINNER * 512)
#define GWO  (DMODEL * 512)
#define GALL (GX + GWQ + 2 * GWKV + GWO)

__global__ __launch_bounds__(256)
void pack_all(const float4* __restrict__ x,  const float4* __restrict__ wq,
              const float4* __restrict__ wk, const float4* __restrict__ wv,
              const float4* __restrict__ wo)
{
    int i = blockIdx.x * 256 + threadIdx.x;
    if (i >= GALL) return;
    if (i < GX) {
        int r = i >> 9, kg = i & 511;
        pack_a4((unsigned short*)g_xf, x[(size_t)r * 512 + kg], r, kg * 4);
    } else if (i < GX + GWQ) {
        int j = i - GX; int c = j >> 9, kg = j & 511;
        pack_b4((unsigned short*)g_wqf, wq[(size_t)c * 512 + kg], c, kg * 4);
    } else if (i < GX + GWQ + GWKV) {
        int j = i - GX - GWQ; int c = j >> 9, kg = j & 511;
        pack_b4((unsigned short*)g_wkf, wk[(size_t)c * 512 + kg], c, kg * 4);
    } else if (i < GX + GWQ + 2 * GWKV) {
        int j = i - GX - GWQ - GWKV; int c = j >> 9, kg = j & 511;
        pack_b4((unsigned short*)g_wvf, wv[(size_t)c * 512 + kg], c, kg * 4);
    } else {
        int j = i - GX - GWQ - 2 * GWKV; int c = j >> 9, kg = j & 511;
        pack_b4((unsigned short*)g_wof, wo[(size_t)c * 512 + kg], c, kg * 4);
    }
}

// ---------------------------------------------------------------------------
// kv_pack: permute fp16 K/V into m16n8k16 attention fragment tiles (pure bits).
// ---------------------------------------------------------------------------
__global__ __launch_bounds__(256)
void kv_pack()
{
    int gidx  = blockIdx.x * 256 + threadIdx.x;
    int lane  = gidx & 31;
    int s_lin = gidx >> 5;
    int s  = s_lin & (SEQ - 1);
    int bk = s_lin >> 11;
    int b  = bk >> 2;
    int kh = bk & 3;

    size_t goff = (size_t)(b * SEQ + s) * KVINNER + kh * DHEAD + lane * 4;
    union { uint2 u; unsigned short h[4]; } ku, vu;
    ku.u = *(const uint2*)(g_kh + goff);
    vu.u = *(const uint2*)(g_vh + goff);

    int r = s & 63;
    int t = s >> 6;
    size_t tb = ((size_t)(b * NKV + kh) * NTILE + t) << 13;
    unsigned short* kdst = (unsigned short*)g_kf16 + tb;
    unsigned short* vdst = (unsigned short*)g_vf16 + tb;

    int d0 = lane * 4;
    {
        int ks = d0 >> 4, dd0 = d0 & 15;
        int breg = (dd0 >> 3) & 1;
        int ni = r >> 3, gK = r & 7;
        int w2 = (((ni & 1) << 1) | breg) << 1;
        int u4 = ((ks * 4 + (ni >> 1)) * 32 + gK * 4) * 8;
        int tigA = (dd0 & 7) >> 1;
        unsigned p0 = (unsigned)ku.h[0] | ((unsigned)ku.h[1] << 16);
        unsigned p1 = (unsigned)ku.h[2] | ((unsigned)ku.h[3] << 16);
        *(unsigned*)(kdst + u4 + tigA * 8 + w2)       = p0;
        *(unsigned*)(kdst + u4 + (tigA + 1) * 8 + w2) = p1;
    }
    {
        int ks2 = r >> 4, kk = r & 15;
        int breg = (kk >> 3) & 1;
        int tigv = (kk & 7) >> 1;
        int hp = kk & 1;
        int ni = d0 >> 3;
        int w2hp = ((((ni & 1) << 1) | breg) << 1) + hp;
        int base = (ks2 * 8 + (ni >> 1)) * 32 * 8 + tigv * 8 + w2hp;
#pragma unroll
        for (int j = 0; j < 4; j++) {
            int gV = (d0 & 7) + j;
            vdst[base + gV * 32] = vu.h[j];
        }
    }
}

// ---------------------------------------------------------------------------
// fp16 GEMM: operands pre-packed fragment-major; 3-stage cp.async pipeline.
// 128x128x32 tiles, 8 warps (2 wm x 4 wn), warp 64x32 via m16n8k16.
// ---------------------------------------------------------------------------
#define GSTAGE 3
#define GEMM16_SMEM (GSTAGE * 16384)   // 48KB

template<bool HALF_OUT>
__device__ __forceinline__
void gemm16_body(const __half* __restrict__ Ag, const __half* __restrict__ Bg,
                 const float* __restrict__ bias, void* __restrict__ C,
                 int N, int bm, int bn, char* smc)
{
    const int tid   = threadIdx.x;
    const int lane  = tid & 31;
    const int wid   = tid >> 5;
    const int gID   = lane >> 2;
    const int tig   = lane & 3;
    const int wmSel = wid & 1;
    const int wnSel = wid >> 1;
    const unsigned sb = (unsigned)__cvta_generic_to_shared(smc);

    float acc[4][4][4];
#pragma unroll
    for (int mi = 0; mi < 4; mi++)
#pragma unroll
        for (int ni = 0; ni < 4; ni++)
#pragma unroll
            for (int j = 0; j < 4; j++) acc[mi][ni][j] = 0.f;

    // prefetch tiles 0,1 into buffers 0,1
#pragma unroll
    for (int p = 0; p < 2; p++) {
        unsigned bo = (unsigned)(p * 16384);
        const __half* Ap = Ag + (size_t)p * HBLK;
        const __half* Bp = Bg + (size_t)p * HBLK;
#pragma unroll
        for (int it = 0; it < 2; it++) {
            int u = tid + it * 256;
            cp16(sb + bo + u * 16, Ap + u * 8);
            cp16(sb + bo + 8192 + u * 16, Bp + u * 8);
        }
        asm volatile("cp.async.commit_group;\n");
    }

    for (int kt = 0; kt < NKT; kt++) {
        int buf = kt % GSTAGE;
        if (kt + 2 < NKT) {
            unsigned bo = (unsigned)(((kt + 2) % GSTAGE) * 16384);
            const __half* An = Ag + (size_t)(kt + 2) * HBLK;
            const __half* Bn = Bg + (size_t)(kt + 2) * HBLK;
#pragma unroll
            for (int it = 0; it < 2; it++) {
                int u = tid + it * 256;
                cp16(sb + bo + u * 16, An + u * 8);
                cp16(sb + bo + 8192 + u * 16, Bn + u * 8);
            }
            asm volatile("cp.async.commit_group;\n");
            asm volatile("cp.async.wait_group 2;\n");
        } else if (kt + 1 < NKT) {
            asm volatile("cp.async.wait_group 1;\n");
        } else {
            asm volatile("cp.async.wait_group 0;\n");
        }
        __syncthreads();

        const uint4* As4 = (const uint4*)(smc + buf * 16384);
        const uint4* Bs4 = (const uint4*)(smc + buf * 16384 + 8192);
#pragma unroll
        for (int ks = 0; ks < 2; ks++) {
            uint4 af[4], bf[2];
#pragma unroll
            for (int mi = 0; mi < 4; mi++)
                af[mi] = As4[(ks * 8 + wmSel * 4 + mi) * 32 + lane];
#pragma unroll
            for (int nip = 0; nip < 2; nip++)
                bf[nip] = Bs4[(ks * 8 + wnSel * 2 + nip) * 32 + lane];
#pragma unroll
            for (int mi = 0; mi < 4; mi++)
#pragma unroll
                for (int nip = 0; nip < 2; nip++) {
                    mma16(acc[mi][2 * nip],     (const unsigned*)&af[mi], bf[nip].x, bf[nip].y);
                    mma16(acc[mi][2 * nip + 1], (const unsigned*)&af[mi], bf[nip].z, bf[nip].w);
                }
        }
        __syncthreads();
    }

    const int wm = wmSel * 64;
    const int wn = wnSel * 32;
#pragma unroll
    for (int mi = 0; mi < 4; mi++) {
        int r = bm + wm + mi * 16 + gID;
#pragma unroll
        for (int ni = 0; ni < 4; ni++) {
            int c = bn + wn + ni * 8 + 2 * tig;
            float2 bv = *(const float2*)(bias + c);
            float o0 = acc[mi][ni][0] + bv.x, o1 = acc[mi][ni][1] + bv.y;
            float o2 = acc[mi][ni][2] + bv.x, o3 = acc[mi][ni][3] + bv.y;
            if (HALF_OUT) {
                __half* Ch = (__half*)C;
                *(__half2*)(Ch + (size_t)r * N + c)       = __floats2half2_rn(o0, o1);
                *(__half2*)(Ch + (size_t)(r + 8) * N + c) = __floats2half2_rn(o2, o3);
            } else {
                float* Cf = (float*)C;
                *(float2*)(Cf + (size_t)r * N + c)       = make_float2(o0, o1);
                *(float2*)(Cf + (size_t)(r + 8) * N + c) = make_float2(o2, o3);
            }
        }
    }
}

// Fused QKV projection: bx 0..15 -> Q, 16..19 -> K, 20..23 -> V
__global__ __launch_bounds__(256, 2)
void qkv_fp16()
{
    __shared__ char smc[GEMM16_SMEM];
    int bx = blockIdx.x, rt = blockIdx.y;
    const __half *B; __half* C; const float* bias; int N, nt;
    if (bx < 16)      { B = g_wqf; C = g_qh; bias = g_bq; N = QINNER;  nt = bx; }
    else if (bx < 20) { B = g_wkf; C = g_kh; bias = g_bk; N = KVINNER; nt = bx - 16; }
    else              { B = g_wvf; C = g_vh; bias = g_bv; N = KVINNER; nt = bx - 20; }
    gemm16_body<true>(g_xf + (size_t)rt * NKT * HBLK, B + (size_t)nt * NKT * HBLK,
                      bias, C, N, rt * 128, nt * 128, smc);
}

__global__ __launch_bounds__(256, 2)
void oproj_fp16(const float* __restrict__ bo, float* __restrict__ C)
{
    __shared__ char smc[GEMM16_SMEM];
    int nt = blockIdx.x, rt = blockIdx.y;
    gemm16_body<false>(g_attf + (size_t)rt * NKT * HBLK, g_wof + (size_t)nt * NKT * HBLK,
                       bo, C, DMODEL, rt * 128, nt * 128, smc);
}

__global__ void set_bias(const float* bq, const float* bk, const float* bv)
{
    if (threadIdx.x == 0) { g_bq = bq; g_bk = bk; g_bv = bv; }
}

// ---------------------------------------------------------------------------
// fp16 flash attention (m16n8k16). K/V pre-packed; double-buffered cp.async;
// bitmask mask; REGISTER-RESIDENT P (S c-layout == PV a-layout, no smem trip).
// ABQ=64, 4 warps, 2 CTAs/SM.
// ---------------------------------------------------------------------------
#define ABQ   64
#define ABK   64
#define ATHR  128
#define TILE_H 8192
#define SMEM_ATTN (4 * 16384)    // 2xKbuf + 2xVbuf = 64KB

__global__ __launch_bounds__(ATHR, 2)
void attn_fp16()
{
    extern __shared__ char smc[];
    const unsigned kfs = (unsigned)__cvta_generic_to_shared(smc);
    const unsigned vfs = kfs + 32768;

    const int tid  = threadIdx.x;
    const int lane = tid & 31;
    const int wid  = tid >> 5;
    const int gID  = lane >> 2;
    const int tig  = lane & 3;
    const int q0   = blockIdx.x * ABQ;
    const int bh   = blockIdx.y;
    const int b    = bh >> 4;
    const int h    = bh & 15;
    const int kh   = h >> 2;
    const float scale = 0.08838834764831845f;

    const __half* kblk0 = g_kf16 + ((size_t)(b * NKV + kh) * NTILE) * TILE_H;
    const __half* vblk0 = g_vf16 + ((size_t)(b * NKV + kh) * NTILE) * TILE_H;

    const int qr0 = q0 + wid * 16 + gID;
    const unsigned* qb0 = (const unsigned*)(g_qh + (size_t)(b * SEQ + qr0) * QINNER + h * DHEAD);
    const unsigned* qb1 = qb0 + 8 * QINNER / 2;
    unsigned qa[8][4];
#pragma unroll
    for (int ks = 0; ks < 8; ks++) {
        qa[ks][0] = qb0[8 * ks + tig];
        qa[ks][1] = qb1[8 * ks + tig];
        qa[ks][2] = qb0[8 * ks + tig + 4];
        qa[ks][3] = qb1[8 * ks + tig + 4];
    }

    float o[16][4];
#pragma unroll
    for (int n = 0; n < 16; n++)
#pragma unroll
        for (int j = 0; j < 4; j++) o[n][j] = 0.f;
    float m0 = -1e30f, m1 = -1e30f, l0 = 0.f, l1 = 0.f;

    const unsigned* mb0 = g_mbits + ((size_t)(b * SEQ) + qr0) * (SEQ / 32);
    const unsigned* mb1 = mb0 + 8 * (SEQ / 32);

#pragma unroll
    for (int it = 0; it < 8; it++) {
        int u = tid + it * ATHR;
        cp16(kfs + u * 16, kblk0 + u * 8);
        cp16(vfs + u * 16, vblk0 + u * 8);
    }
    asm volatile("cp.async.commit_group;\n");

    for (int t = 0; t < NTILE; t++) {
        int buf = t & 1;
        if (t + 1 < NTILE) {
            int bn = buf ^ 1;
            const __half* kb = kblk0 + (size_t)(t + 1) * TILE_H;
            const __half* vb = vblk0 + (size_t)(t + 1) * TILE_H;
#pragma unroll
            for (int it = 0; it < 8; it++) {
                int u = tid + it * ATHR;
                cp16(kfs + bn * 16384 + u * 16, kb + u * 8);
                cp16(vfs + bn * 16384 + u * 16, vb + u * 8);
            }
            asm volatile("cp.async.commit_group;\n");
            asm volatile("cp.async.wait_group 1;\n");
        } else {
            asm volatile("cp.async.wait_group 0;\n");
        }
        __syncthreads();

        const uint4* Kf = (const uint4*)(smc + buf * 16384);
        const uint4* Vf = (const uint4*)(smc + 32768 + buf * 16384);

        float s[8][4];
#pragma unroll
        for (int ni = 0; ni < 8; ni++)
#pragma unroll
            for (int j = 0; j < 4; j++) s[ni][j] = 0.f;

#pragma unroll
        for (int ks = 0; ks < 8; ks++) {
#pragma unroll
            for (int nip = 0; nip < 4; nip++) {
                uint4 kf = Kf[(ks * 4 + nip) * 32 + lane];
                mma16(s[2 * nip],     qa[ks], kf.x, kf.y);
                mma16(s[2 * nip + 1], qa[ks], kf.z, kf.w);
            }
        }

        // ---- scale + mask (bitmask, all-ones fast path) + online softmax ----
        uint2 w0 = *(const uint2*)(mb0 + t * 2);
        uint2 w1 = *(const uint2*)(mb1 + t * 2);
        unsigned long long M0 = ((unsigned long long)w0.y << 32) | w0.x;
        unsigned long long M1 = ((unsigned long long)w1.y << 32) | w1.x;

        float nm0 = m0, nm1 = m1;
        if ((M0 & M1) == 0xFFFFFFFFFFFFFFFFull) {
#pragma unroll
            for (int ni = 0; ni < 8; ni++) {
                s[ni][0] *= scale; s[ni][1] *= scale;
                s[ni][2] *= scale; s[ni][3] *= scale;
                nm0 = fmaxf(nm0, fmaxf(s[ni][0], s[ni][1]));
                nm1 = fmaxf(nm1, fmaxf(s[ni][2], s[ni][3]));
            }
        } else {
#pragma unroll
            for (int ni = 0; ni < 8; ni++) {
                int p = ni * 8 + 2 * tig;
                s[ni][0] = ((M0 >> p) & 1)       ? s[ni][0] * scale : -1e30f;
                s[ni][1] = ((M0 >> (p + 1)) & 1) ? s[ni][1] * scale : -1e30f;
                s[ni][2] = ((M1 >> p) & 1)       ? s[ni][2] * scale : -1e30f;
                s[ni][3] = ((M1 >> (p + 1)) & 1) ? s[ni][3] * scale : -1e30f;
                nm0 = fmaxf(nm0, fmaxf(s[ni][0], s[ni][1]));
                nm1 = fmaxf(nm1, fmaxf(s[ni][2], s[ni][3]));
            }
        }
        nm0 = fmaxf(nm0, __shfl_xor_sync(0xffffffffu, nm0, 1));
        nm0 = fmaxf(nm0, __shfl_xor_sync(0xffffffffu, nm0, 2));
        nm1 = fmaxf(nm1, __shfl_xor_sync(0xffffffffu, nm1, 1));
        nm1 = fmaxf(nm1, __shfl_xor_sync(0xffffffffu, nm1, 2));

        float corr0 = __expf(m0 - nm0);
        float corr1 = __expf(m1 - nm1);
        m0 = nm0; m1 = nm1;

        float rs0 = 0.f, rs1 = 0.f;
#pragma unroll
        for (int ni = 0; ni < 8; ni++) {
            s[ni][0] = (s[ni][0] > -1e29f) ? __expf(s[ni][0] - m0) : 0.f;
            s[ni][1] = (s[ni][1] > -1e29f) ? __expf(s[ni][1] - m0) : 0.f;
            s[ni][2] = (s[ni][2] > -1e29f) ? __expf(s[ni][2] - m1) : 0.f;
            s[ni][3] = (s[ni][3] > -1e29f) ? __expf(s[ni][3] - m1) : 0.f;
            rs0 += s[ni][0] + s[ni][1];
            rs1 += s[ni][2] + s[ni][3];
        }
        rs0 += __shfl_xor_sync(0xffffffffu, rs0, 1);
        rs0 += __shfl_xor_sync(0xffffffffu, rs0, 2);
        rs1 += __shfl_xor_sync(0xffffffffu, rs1, 1);
        rs1 += __shfl_xor_sync(0xffffffffu, rs1, 2);
        l0 = l0 * corr0 + rs0;
        l1 = l1 * corr1 + rs1;

#pragma unroll
        for (int n = 0; n < 16; n++) {
            o[n][0] *= corr0; o[n][1] *= corr0;
            o[n][2] *= corr1; o[n][3] *= corr1;
        }

        // ---- O += P @ V ; P a-frags built directly from S c-layout regs ----
#pragma unroll
        for (int ks2 = 0; ks2 < 4; ks2++) {
            unsigned pa[4];
            pa[0] = pack2h(s[2 * ks2][0],     s[2 * ks2][1]);      // row gID,   keys 16ks2+2tig
            pa[1] = pack2h(s[2 * ks2][2],     s[2 * ks2][3]);      // row gID+8, keys 16ks2+2tig
            pa[2] = pack2h(s[2 * ks2 + 1][0], s[2 * ks2 + 1][1]);  // row gID,   keys +8
            pa[3] = pack2h(s[2 * ks2 + 1][2], s[2 * ks2 + 1][3]);  // row gID+8, keys +8
#pragma unroll
            for (int nip = 0; nip < 8; nip++) {
                uint4 vf = Vf[(ks2 * 8 + nip) * 32 + lane];
                mma16(o[2 * nip],     pa, vf.x, vf.y);
                mma16(o[2 * nip + 1], pa, vf.z, vf.w);
            }
        }
        __syncthreads();
    }

    // ---- normalize + store att in fragment-major fp16 blocks ----
    float inv0 = (l0 > 0.f) ? (1.f / l0) : 0.f;
    float inv1 = (l1 > 0.f) ? (1.f / l1) : 0.f;
    int rr = (b * SEQ + qr0) & 127;
    int mi = rr >> 4;
    size_t rowblk = (size_t)((b * SEQ + qr0) >> 7) * NKT;
    unsigned short* attf = (unsigned short*)g_attf;
#pragma unroll
    for (int ni = 0; ni < 16; ni++) {
        int c    = h * DHEAD + ni * 8 + 2 * tig;
        int kt   = c >> 5;
        int ks   = (ni & 3) >> 1;
        int breg = ni & 1;
        unsigned short* base = attf + (rowblk + kt) * HBLK
            + ((ks * 8 + mi) * 32 + gID * 4 + tig) * 8 + (breg << 1) * 2;
        *(unsigned*)(base)     = pack2h(o[ni][0] * inv0, o[ni][1] * inv0);
        *(unsigned*)(base + 2) = pack2h(o[ni][2] * inv1, o[ni][3] * inv1);
    }
}

// ---------------------------------------------------------------------------
// Launch
// ---------------------------------------------------------------------------
extern "C" void kernel_launch(void* const* d_in, const int* in_sizes, int n_in,
                              void* d_out, int out_size)
{
    const float* x    = (const float*)d_in[0];
    const int*   mask = (const int*)  d_in[1];
    const float* Wq   = (const float*)d_in[2];
    const float* bq   = (const float*)d_in[3];
    const float* Wk   = (const float*)d_in[4];
    const float* bk   = (const float*)d_in[5];
    const float* Wv   = (const float*)d_in[6];
    const float* bv   = (const float*)d_in[7];
    const float* Wo   = (const float*)d_in[8];
    const float* bo   = (const float*)d_in[9];
    float* out = (float*)d_out;

    cudaFuncSetAttribute(attn_fp16, cudaFuncAttributeMaxDynamicSharedMemorySize, SMEM_ATTN);

    dim3 thr(256);
    set_bias<<<1, 32>>>(bq, bk, bv);
    mask_pack<<<(MWORDS + 255) / 256, thr>>>((const int4*)mask);
    pack_all<<<(GALL + 255) / 256, thr>>>(
        (const float4*)x, (const float4*)Wq, (const float4*)Wk,
        (const float4*)Wv, (const float4*)Wo);
    qkv_fp16<<<dim3(24, MROWS / 128), thr>>>();
    kv_pack<<<(BB * NKV * SEQ * 32) / 256, thr>>>();
    attn_fp16<<<dim3(SEQ / ABQ, BB * NHEAD), dim3(ATHR), SMEM_ATTN>>>();
    oproj_fp16<<<dim3(DMODEL / 128, MROWS / 128), thr>>>(bo, out);
}